// round 1
// baseline (speedup 1.0000x reference)
#include <cuda_runtime.h>
#include <math.h>

// Problem constants
#define BTT     16          // b*t = 4*4
#define NM      1024        // tensor tokens per (b,t)
#define NL      64          // latent tokens per (b,t)
#define NKV     1088        // NM + NL
#define DIMM    128
#define HEADS   8
#define DHEAD   256         // INNER / HEADS
#define INNER   2048
#define QSCALE  0.08838834764831845f   // 128^-0.5

// Static device scratch (no allocations allowed)
static __device__ float g_q [BTT * NL  * INNER];                 //  8.4 MB (q * scale)
static __device__ float g_k [BTT * NKV * INNER];                 // 142.6 MB
static __device__ float g_v [BTT * NKV * INNER];                 // 142.6 MB
static __device__ float g_s [BTT * HEADS * NL * NKV];            // 35.7 MB (sim / attn)
static __device__ float g_ao[BTT * NL  * INNER];                 //  8.4 MB (attn @ v)

// ---------------------------------------------------------------------------
// Common 64x64 tile, BK=16, 256 threads, 4x4 micro-tile per thread.
// As/Bs stored [k][m]/[k][n] with row stride 68 (16B-aligned, conflict-free).
// All problem dims are exact multiples of the tile sizes -> no bounds checks.
// ---------------------------------------------------------------------------

__device__ __forceinline__ void gemm_nn_core(
    const float* __restrict__ A, const float* __restrict__ B, float* __restrict__ C,
    int lda, int ldb, int ldc, int K, float alpha, int m0, int n0)
{
    __shared__ float As[16][68];
    __shared__ float Bs[16][68];
    const int t  = threadIdx.x;
    const int tx = t & 15, ty = t >> 4;
    const int am = t >> 2, ak = (t & 3) << 2;    // A loader: row am, 4 cols at ak
    const int bk = t >> 4, bn = (t & 15) << 2;   // B loader: row bk, 4 cols at bn
    const float* Ap = A + (size_t)(m0 + am) * lda + ak;
    const float* Bp = B + (size_t)bk * ldb + n0 + bn;
    float acc[4][4] = {};
    for (int kb = 0; kb < K; kb += 16) {
        float4 a = *(const float4*)(Ap + kb);
        float4 b = *(const float4*)(Bp + (size_t)kb * ldb);
        As[ak+0][am] = a.x; As[ak+1][am] = a.y; As[ak+2][am] = a.z; As[ak+3][am] = a.w;
        *(float4*)&Bs[bk][bn] = b;
        __syncthreads();
        #pragma unroll
        for (int k = 0; k < 16; ++k) {
            float4 av = *(const float4*)&As[k][ty << 2];
            float4 bv = *(const float4*)&Bs[k][tx << 2];
            acc[0][0] += av.x*bv.x; acc[0][1] += av.x*bv.y; acc[0][2] += av.x*bv.z; acc[0][3] += av.x*bv.w;
            acc[1][0] += av.y*bv.x; acc[1][1] += av.y*bv.y; acc[1][2] += av.y*bv.z; acc[1][3] += av.y*bv.w;
            acc[2][0] += av.z*bv.x; acc[2][1] += av.z*bv.y; acc[2][2] += av.z*bv.z; acc[2][3] += av.z*bv.w;
            acc[3][0] += av.w*bv.x; acc[3][1] += av.w*bv.y; acc[3][2] += av.w*bv.z; acc[3][3] += av.w*bv.w;
        }
        __syncthreads();
    }
    #pragma unroll
    for (int i = 0; i < 4; ++i) {
        float4 r;
        r.x = acc[i][0]*alpha; r.y = acc[i][1]*alpha; r.z = acc[i][2]*alpha; r.w = acc[i][3]*alpha;
        *(float4*)&C[(size_t)(m0 + (ty << 2) + i) * ldc + n0 + (tx << 2)] = r;
    }
}

// NT variant: B is [N, K] row-major; C[m][n] = sum_k A[m][k] * B[n][k]
__device__ __forceinline__ void gemm_nt_core(
    const float* __restrict__ A, const float* __restrict__ Bm, float* __restrict__ C,
    int lda, int ldb, int ldc, int K, int m0, int n0)
{
    __shared__ float As[16][68];
    __shared__ float Bs[16][68];
    const int t  = threadIdx.x;
    const int tx = t & 15, ty = t >> 4;
    const int am = t >> 2, ak = (t & 3) << 2;
    const int bn = t >> 2, bq = (t & 3) << 2;    // B loader: row (n0+bn), 4 k-cols at bq
    const float* Ap = A  + (size_t)(m0 + am) * lda + ak;
    const float* Bp = Bm + (size_t)(n0 + bn) * ldb + bq;
    float acc[4][4] = {};
    for (int kb = 0; kb < K; kb += 16) {
        float4 a = *(const float4*)(Ap + kb);
        float4 b = *(const float4*)(Bp + kb);
        As[ak+0][am] = a.x; As[ak+1][am] = a.y; As[ak+2][am] = a.z; As[ak+3][am] = a.w;
        Bs[bq+0][bn] = b.x; Bs[bq+1][bn] = b.y; Bs[bq+2][bn] = b.z; Bs[bq+3][bn] = b.w;
        __syncthreads();
        #pragma unroll
        for (int k = 0; k < 16; ++k) {
            float4 av = *(const float4*)&As[k][ty << 2];
            float4 bv = *(const float4*)&Bs[k][tx << 2];
            acc[0][0] += av.x*bv.x; acc[0][1] += av.x*bv.y; acc[0][2] += av.x*bv.z; acc[0][3] += av.x*bv.w;
            acc[1][0] += av.y*bv.x; acc[1][1] += av.y*bv.y; acc[1][2] += av.y*bv.z; acc[1][3] += av.y*bv.w;
            acc[2][0] += av.z*bv.x; acc[2][1] += av.z*bv.y; acc[2][2] += av.z*bv.z; acc[2][3] += av.z*bv.w;
            acc[3][0] += av.w*bv.x; acc[3][1] += av.w*bv.y; acc[3][2] += av.w*bv.z; acc[3][3] += av.w*bv.w;
        }
        __syncthreads();
    }
    #pragma unroll
    for (int i = 0; i < 4; ++i) {
        float4 r;
        r.x = acc[i][0]; r.y = acc[i][1]; r.z = acc[i][2]; r.w = acc[i][3];
        *(float4*)&C[(size_t)(m0 + (ty << 2) + i) * ldc + n0 + (tx << 2)] = r;
    }
}

// ---------------------------------------------------------------------------
// Kernels
// ---------------------------------------------------------------------------

// q = (latents @ Wq) * SCALE   : [1024,128] @ [128,2048]
__global__ void k_proj_q(const float* __restrict__ latents, const float* __restrict__ Wq)
{
    gemm_nn_core(latents, Wq, g_q, DIMM, INNER, INNER, DIMM, QSCALE,
                 blockIdx.y * 64, blockIdx.x * 64);
}

// kv = concat(tensor, latents) @ Wkv : [17408,128] @ [128,4096] -> split into g_k / g_v
__global__ void k_proj_kv(const float* __restrict__ tensor, const float* __restrict__ latents,
                          const float* __restrict__ Wkv)
{
    __shared__ float As[16][68];
    __shared__ float Bs[16][68];
    const int m0 = blockIdx.y * 64, n0 = blockIdx.x * 64;
    const int t  = threadIdx.x;
    const int tx = t & 15, ty = t >> 4;
    const int am = t >> 2, ak = (t & 3) << 2;
    const int bk = t >> 4, bn = (t & 15) << 2;

    // per-row gather from the concat: row r -> (bt, j); j<1024 from tensor else latents
    const int r  = m0 + am;
    const int bt = r / NKV;
    const int j  = r - bt * NKV;
    const float* Ap = (j < NM)
        ? tensor  + (size_t)(bt * NM + j)        * DIMM + ak
        : latents + (size_t)(bt * NL + (j - NM)) * DIMM + ak;
    const float* Bp = Wkv + (size_t)bk * (2 * INNER) + n0 + bn;

    float acc[4][4] = {};
    for (int kb = 0; kb < DIMM; kb += 16) {
        float4 a = *(const float4*)(Ap + kb);
        float4 b = *(const float4*)(Bp + (size_t)kb * (2 * INNER));
        As[ak+0][am] = a.x; As[ak+1][am] = a.y; As[ak+2][am] = a.z; As[ak+3][am] = a.w;
        *(float4*)&Bs[bk][bn] = b;
        __syncthreads();
        #pragma unroll
        for (int k = 0; k < 16; ++k) {
            float4 av = *(const float4*)&As[k][ty << 2];
            float4 bv = *(const float4*)&Bs[k][tx << 2];
            acc[0][0] += av.x*bv.x; acc[0][1] += av.x*bv.y; acc[0][2] += av.x*bv.z; acc[0][3] += av.x*bv.w;
            acc[1][0] += av.y*bv.x; acc[1][1] += av.y*bv.y; acc[1][2] += av.y*bv.z; acc[1][3] += av.y*bv.w;
            acc[2][0] += av.z*bv.x; acc[2][1] += av.z*bv.y; acc[2][2] += av.z*bv.z; acc[2][3] += av.z*bv.w;
            acc[3][0] += av.w*bv.x; acc[3][1] += av.w*bv.y; acc[3][2] += av.w*bv.z; acc[3][3] += av.w*bv.w;
        }
        __syncthreads();
    }
    // whole 64-wide n-tile lands entirely in k half or v half (2048 % 64 == 0)
    float* dst = (n0 < INNER) ? g_k : g_v;
    const int col = n0 & (INNER - 1);
    #pragma unroll
    for (int i = 0; i < 4; ++i) {
        float4 rr;
        rr.x = acc[i][0]; rr.y = acc[i][1]; rr.z = acc[i][2]; rr.w = acc[i][3];
        *(float4*)&dst[(size_t)(m0 + (ty << 2) + i) * INNER + col + (tx << 2)] = rr;
    }
}

// sim = q_h @ k_h^T per (bt,h): [64,256] @ [1088,256]^T -> [64,1088]
__global__ void k_sim()
{
    const int z  = blockIdx.z;            // 0..127 : bt*8 + h
    const int bt = z >> 3, h = z & 7;
    const float* A = g_q + (size_t)bt * NL  * INNER + h * DHEAD;   // lda = INNER
    const float* B = g_k + (size_t)bt * NKV * INNER + h * DHEAD;   // ldb = INNER
    float*       C = g_s + (size_t)z * NL * NKV;                   // ldc = NKV
    gemm_nt_core(A, B, C, INNER, INNER, NKV, DHEAD, blockIdx.y * 64, blockIdx.x * 64);
}

// row softmax over g_s: 8192 rows x 1088, one warp per row, row held in registers
__global__ void k_softmax()
{
    const int row  = blockIdx.x * 8 + (threadIdx.x >> 5);
    const int lane = threadIdx.x & 31;
    float* p = g_s + (size_t)row * NKV;
    float v[34];
    float mx = -INFINITY;
    #pragma unroll
    for (int i = 0; i < 34; ++i) { v[i] = p[lane + i * 32]; mx = fmaxf(mx, v[i]); }
    #pragma unroll
    for (int o = 16; o; o >>= 1) mx = fmaxf(mx, __shfl_xor_sync(0xffffffffu, mx, o));
    float s = 0.f;
    #pragma unroll
    for (int i = 0; i < 34; ++i) { v[i] = expf(v[i] - mx); s += v[i]; }
    #pragma unroll
    for (int o = 16; o; o >>= 1) s += __shfl_xor_sync(0xffffffffu, s, o);
    const float inv = 1.0f / s;
    #pragma unroll
    for (int i = 0; i < 34; ++i) p[lane + i * 32] = v[i] * inv;
}

// out_h = attn @ v_h per (bt,h): [64,1088] @ [1088,256] -> written into g_ao head slice
__global__ void k_pv()
{
    const int z  = blockIdx.z;
    const int bt = z >> 3, h = z & 7;
    const float* A = g_s  + (size_t)z * NL * NKV;                    // lda = NKV
    const float* B = g_v  + (size_t)bt * NKV * INNER + h * DHEAD;    // ldb = INNER
    float*       C = g_ao + (size_t)bt * NL  * INNER + h * DHEAD;    // ldc = INNER
    gemm_nn_core(A, B, C, NKV, INNER, INNER, NKV, 1.0f, blockIdx.y * 64, blockIdx.x * 64);
}

// final: out = g_ao @ Wo : [1024,2048] @ [2048,128]
__global__ void k_out(const float* __restrict__ Wo, float* __restrict__ out)
{
    gemm_nn_core(g_ao, Wo, out, INNER, DIMM, DIMM, INNER, 1.0f,
                 blockIdx.y * 64, blockIdx.x * 64);
}

// ---------------------------------------------------------------------------

extern "C" void kernel_launch(void* const* d_in, const int* in_sizes, int n_in,
                              void* d_out, int out_size)
{
    const float* tensor  = (const float*)d_in[0];   // [4,4,1024,128]
    const float* latents = (const float*)d_in[1];   // [4,4,64,128]
    const float* Wq      = (const float*)d_in[2];   // [128,2048]
    const float* Wkv     = (const float*)d_in[3];   // [128,4096]
    const float* Wo      = (const float*)d_in[4];   // [2048,128]
    float*       out     = (float*)d_out;           // [4,4,64,128]

    (void)in_sizes; (void)n_in; (void)out_size;

    k_proj_q <<<dim3(INNER/64, (BTT*NL)/64), 256>>>(latents, Wq);
    k_proj_kv<<<dim3((2*INNER)/64, (BTT*NKV)/64), 256>>>(tensor, latents, Wkv);
    k_sim    <<<dim3(NKV/64, 1, BTT*HEADS), 256>>>();
    k_softmax<<<(BTT*HEADS*NL)/8, 256>>>();
    k_pv     <<<dim3(DHEAD/64, 1, BTT*HEADS), 256>>>();
    k_out    <<<dim3(DIMM/64, (BTT*NL)/64), 256>>>(Wo, out);
}

// round 2
// speedup vs baseline: 1.4276x; 1.4276x over previous
#include <cuda_runtime.h>
#include <math.h>

// Problem constants
#define BTT     16
#define NM      1024
#define NL      64
#define NKV     1088
#define DIMM    128
#define HEADS   8
#define DHEAD   256
#define INNER   2048
#define QSCALE  0.08838834764831845f   // 128^-0.5

// GEMM tiling
#define BM 64
#define BN 128
#define BK 32
#define NTHREADS 128

// Static device scratch
static __device__ float g_in[BTT * NKV * DIMM];          //  8.9 MB concat(tensor, latents)
static __device__ float g_q [BTT * NL  * INNER];         //  8.4 MB (q * scale)
static __device__ float g_k [BTT * NKV * INNER];         // 142.6 MB
static __device__ float g_v [BTT * NKV * INNER];         // 142.6 MB
static __device__ float g_s [BTT * HEADS * NL * NKV];    // 35.7 MB
static __device__ float g_ao[BTT * NL  * INNER];         //  8.4 MB

// fp32 -> tf32 (round-to-nearest), kept in a float container
__device__ __forceinline__ float cf(float x){
    unsigned u; asm("cvt.rna.tf32.f32 %0, %1;" : "=r"(u) : "f"(x));
    return __uint_as_float(u);
}

__device__ __forceinline__ void mma8(float* d, const unsigned* a, const unsigned* b){
    asm volatile("mma.sync.aligned.m16n8k8.row.col.f32.tf32.tf32.f32 "
        "{%0,%1,%2,%3}, {%4,%5,%6,%7}, {%8,%9}, {%0,%1,%2,%3};"
        : "+f"(d[0]), "+f"(d[1]), "+f"(d[2]), "+f"(d[3])
        : "r"(a[0]), "r"(a[1]), "r"(a[2]), "r"(a[3]), "r"(b[0]), "r"(b[1]));
}

// ---------------------------------------------------------------------------
// tf32 MMA core: CTA tile 64 x 128, BK=32, 4 warps, warp tile 32x64.
// A, B, C pointers are pre-offset to the tile origin. TRANSB: B given as
// [N][K] row-major (ldb = its row stride). GUARDN: B-rows / C-cols beyond
// Nrem are zero-padded / skipped.
// Smem strides 72 / 136 (== 8 mod 32) -> conflict-free fragment loads.
// ---------------------------------------------------------------------------
template<bool TRANSB, bool GUARDN>
__device__ __forceinline__ void mma_core(
    const float* __restrict__ A, int lda,
    const float* __restrict__ B, int ldb,
    float* __restrict__ C, int ldc,
    int K, int Nrem, float alpha)
{
    __shared__ float As[BK][72];
    __shared__ float Bs[BK][136];
    const int t    = threadIdx.x;
    const int warp = t >> 5, lane = t & 31;
    const int grp  = lane >> 2, qid = lane & 3;
    const int wm   = (warp & 1) * 32, wn = (warp >> 1) * 64;

    // A loader: row t>>1 (0..63), k base (t&1)*16, 4 x float4
    const int arow = t >> 1, ak0 = (t & 1) * 16;
    const float* Ap = A + (size_t)arow * lda + ak0;
    // B loader (NN): row t>>2 (0..31), col base (t&3)*32, 8 x float4
    const int brow = t >> 2, bcol = (t & 3) * 32;
    const float* Bp;
    bool bval = true;
    if (TRANSB) { Bp = B + (size_t)t * ldb; if (GUARDN) bval = (t < Nrem); }
    else        { Bp = B + (size_t)brow * ldb + bcol; }

    float4 ar[4], br[8];
    float acc[2][8][4];
    #pragma unroll
    for (int f = 0; f < 2; f++)
        #pragma unroll
        for (int j = 0; j < 8; j++)
            #pragma unroll
            for (int i = 0; i < 4; i++) acc[f][j][i] = 0.f;

    const int nk = K / BK;

    // prefetch chunk 0
    #pragma unroll
    for (int i = 0; i < 4; i++) ar[i] = *(const float4*)(Ap + 4*i);
    if (TRANSB) {
        #pragma unroll
        for (int i = 0; i < 8; i++)
            br[i] = bval ? *(const float4*)(Bp + 4*i) : make_float4(0.f,0.f,0.f,0.f);
    } else {
        #pragma unroll
        for (int i = 0; i < 8; i++) br[i] = *(const float4*)(Bp + 4*i);
    }

    for (int c = 0; c < nk; c++) {
        // store staged regs to smem (with tf32 rounding)
        #pragma unroll
        for (int i = 0; i < 4; i++) {
            int kc = ak0 + 4*i;
            As[kc+0][arow] = cf(ar[i].x); As[kc+1][arow] = cf(ar[i].y);
            As[kc+2][arow] = cf(ar[i].z); As[kc+3][arow] = cf(ar[i].w);
        }
        if (TRANSB) {
            #pragma unroll
            for (int i = 0; i < 8; i++) {
                int kc = 4*i;
                Bs[kc+0][t] = cf(br[i].x); Bs[kc+1][t] = cf(br[i].y);
                Bs[kc+2][t] = cf(br[i].z); Bs[kc+3][t] = cf(br[i].w);
            }
        } else {
            #pragma unroll
            for (int i = 0; i < 8; i++) {
                float4 v;
                v.x = cf(br[i].x); v.y = cf(br[i].y);
                v.z = cf(br[i].z); v.w = cf(br[i].w);
                *(float4*)&Bs[brow][bcol + 4*i] = v;
            }
        }
        __syncthreads();

        // prefetch next chunk (overlaps with compute)
        if (c + 1 < nk) {
            const float* Ap2 = Ap + (c + 1) * BK;
            #pragma unroll
            for (int i = 0; i < 4; i++) ar[i] = *(const float4*)(Ap2 + 4*i);
            if (TRANSB) {
                const float* Bp2 = Bp + (c + 1) * BK;
                #pragma unroll
                for (int i = 0; i < 8; i++)
                    br[i] = bval ? *(const float4*)(Bp2 + 4*i) : make_float4(0.f,0.f,0.f,0.f);
            } else {
                const float* Bp2 = Bp + (size_t)(c + 1) * BK * ldb;
                #pragma unroll
                for (int i = 0; i < 8; i++) br[i] = *(const float4*)(Bp2 + 4*i);
            }
        }

        // compute 4 k8-steps
        #pragma unroll
        for (int kk = 0; kk < BK; kk += 8) {
            unsigned a[2][4], b[8][2];
            #pragma unroll
            for (int f = 0; f < 2; f++) {
                a[f][0] = __float_as_uint(As[kk+qid  ][wm+16*f+grp  ]);
                a[f][1] = __float_as_uint(As[kk+qid  ][wm+16*f+grp+8]);
                a[f][2] = __float_as_uint(As[kk+qid+4][wm+16*f+grp  ]);
                a[f][3] = __float_as_uint(As[kk+qid+4][wm+16*f+grp+8]);
            }
            #pragma unroll
            for (int j = 0; j < 8; j++) {
                b[j][0] = __float_as_uint(Bs[kk+qid  ][wn+8*j+grp]);
                b[j][1] = __float_as_uint(Bs[kk+qid+4][wn+8*j+grp]);
            }
            #pragma unroll
            for (int f = 0; f < 2; f++)
                #pragma unroll
                for (int j = 0; j < 8; j++) mma8(acc[f][j], a[f], b[j]);
        }
        __syncthreads();
    }

    // epilogue
    #pragma unroll
    for (int f = 0; f < 2; f++) {
        int r0 = wm + 16*f + grp;
        #pragma unroll
        for (int j = 0; j < 8; j++) {
            int col = wn + 8*j + 2*qid;
            if (GUARDN && col >= Nrem) continue;
            *(float2*)&C[(size_t)r0 * ldc + col] =
                make_float2(acc[f][j][0]*alpha, acc[f][j][1]*alpha);
            *(float2*)&C[(size_t)(r0+8) * ldc + col] =
                make_float2(acc[f][j][2]*alpha, acc[f][j][3]*alpha);
        }
    }
}

// ---------------------------------------------------------------------------
// Kernels
// ---------------------------------------------------------------------------

// Build concat(tensor, latents) -> g_in [BTT*NKV, 128]
__global__ void k_concat(const float* __restrict__ tensor, const float* __restrict__ latents)
{
    int idx = blockIdx.x * 256 + threadIdx.x;      // float4 index
    int row = idx >> 5, c4 = idx & 31;
    int bt = row / NKV, j = row - bt * NKV;
    const float* src = (j < NM)
        ? tensor  + (size_t)(bt * NM + j)        * DIMM
        : latents + (size_t)(bt * NL + (j - NM)) * DIMM;
    ((float4*)(g_in + (size_t)row * DIMM))[c4] = ((const float4*)src)[c4];
}

// q = (latents @ Wq) * SCALE : [1024,128] @ [128,2048]
__global__ void __launch_bounds__(NTHREADS) k_proj_q(
    const float* __restrict__ latents, const float* __restrict__ Wq)
{
    int m0 = blockIdx.y * BM, n0 = blockIdx.x * BN;
    mma_core<false,false>(latents + (size_t)m0 * DIMM, DIMM, Wq + n0, INNER,
                          g_q + (size_t)m0 * INNER + n0, INNER, DIMM, BN, QSCALE);
}

// kv = g_in @ Wkv : [17408,128] @ [128,4096] -> split g_k / g_v
__global__ void __launch_bounds__(NTHREADS) k_proj_kv(const float* __restrict__ Wkv)
{
    int m0 = blockIdx.y * BM, n0 = blockIdx.x * BN;
    float* dst = (n0 < INNER) ? g_k : g_v;
    int nc = n0 & (INNER - 1);
    mma_core<false,false>(g_in + (size_t)m0 * DIMM, DIMM, Wkv + n0, 2 * INNER,
                          dst + (size_t)m0 * INNER + nc, INNER, DIMM, BN, 1.0f);
}

// sim = q_h @ k_h^T per (bt,h): [64,256] @ [1088,256]^T
__global__ void __launch_bounds__(NTHREADS) k_sim()
{
    int z = blockIdx.z, bt = z >> 3, h = z & 7;
    int n0 = blockIdx.x * BN;
    const float* A = g_q + (size_t)bt * NL * INNER + h * DHEAD;
    const float* B = g_k + ((size_t)bt * NKV + n0) * INNER + h * DHEAD;
    float*       C = g_s + (size_t)z * NL * NKV + n0;
    mma_core<true,true>(A, INNER, B, INNER, C, NKV, DHEAD, NKV - n0, 1.0f);
}

// row softmax: 8192 rows x 1088, one warp per row, row in registers
__global__ void k_softmax()
{
    const int row  = blockIdx.x * 8 + (threadIdx.x >> 5);
    const int lane = threadIdx.x & 31;
    float* p = g_s + (size_t)row * NKV;
    float v[34];
    float mx = -INFINITY;
    #pragma unroll
    for (int i = 0; i < 34; ++i) { v[i] = p[lane + i * 32]; mx = fmaxf(mx, v[i]); }
    #pragma unroll
    for (int o = 16; o; o >>= 1) mx = fmaxf(mx, __shfl_xor_sync(0xffffffffu, mx, o));
    float s = 0.f;
    #pragma unroll
    for (int i = 0; i < 34; ++i) { v[i] = expf(v[i] - mx); s += v[i]; }
    #pragma unroll
    for (int o = 16; o; o >>= 1) s += __shfl_xor_sync(0xffffffffu, s, o);
    const float inv = 1.0f / s;
    #pragma unroll
    for (int i = 0; i < 34; ++i) p[lane + i * 32] = v[i] * inv;
}

// out_h = attn @ v_h per (bt,h): [64,1088] @ [1088,256]
__global__ void __launch_bounds__(NTHREADS) k_pv()
{
    int z = blockIdx.z, bt = z >> 3, h = z & 7;
    int n0 = blockIdx.x * BN;
    const float* A = g_s  + (size_t)z * NL * NKV;
    const float* B = g_v  + (size_t)bt * NKV * INNER + h * DHEAD + n0;
    float*       C = g_ao + (size_t)bt * NL  * INNER + h * DHEAD + n0;
    mma_core<false,false>(A, NKV, B, INNER, C, INNER, NKV, BN, 1.0f);
}

// final: out = g_ao @ Wo : [1024,2048] @ [2048,128]
__global__ void __launch_bounds__(NTHREADS) k_out(
    const float* __restrict__ Wo, float* __restrict__ out)
{
    int m0 = blockIdx.y * BM;
    mma_core<false,false>(g_ao + (size_t)m0 * INNER, INNER, Wo, DIMM,
                          out + (size_t)m0 * DIMM, DIMM, INNER, BN, 1.0f);
}

// ---------------------------------------------------------------------------

extern "C" void kernel_launch(void* const* d_in, const int* in_sizes, int n_in,
                              void* d_out, int out_size)
{
    const float* tensor  = (const float*)d_in[0];   // [4,4,1024,128]
    const float* latents = (const float*)d_in[1];   // [4,4,64,128]
    const float* Wq      = (const float*)d_in[2];   // [128,2048]
    const float* Wkv     = (const float*)d_in[3];   // [128,4096]
    const float* Wo      = (const float*)d_in[4];   // [2048,128]
    float*       out     = (float*)d_out;           // [4,4,64,128]

    (void)in_sizes; (void)n_in; (void)out_size;

    k_concat <<<(BTT * NKV * DIMM / 4) / 256, 256>>>(tensor, latents);
    k_proj_q <<<dim3(INNER / BN, (BTT * NL) / BM), NTHREADS>>>(latents, Wq);
    k_proj_kv<<<dim3(2 * INNER / BN, (BTT * NKV) / BM), NTHREADS>>>(Wkv);
    k_sim    <<<dim3((NKV + BN - 1) / BN, 1, BTT * HEADS), NTHREADS>>>();
    k_softmax<<<(BTT * HEADS * NL) / 8, 256>>>();
    k_pv     <<<dim3(DHEAD / BN, 1, BTT * HEADS), NTHREADS>>>();
    k_out    <<<dim3(1, (BTT * NL) / BM), NTHREADS>>>(Wo, out);
}

// round 3
// speedup vs baseline: 5.1527x; 3.6093x over previous
#include <cuda_runtime.h>
#include <math.h>

// Problem constants
#define BTT     16
#define NM      1024
#define NL      64
#define NKV     1088
#define DIMM    128
#define HEADS   8
#define INNER   2048
#define QSCALE  0.08838834764831845f   // 128^-0.5

// MMA GEMM tiling
#define BM 64
#define BN 128
#define BK 32
#define NTHREADS 128

// Static device scratch
static __device__ float g_in[BTT * NKV * DIMM];            // 8.9 MB concat(tensor, latents)
static __device__ float g_m [HEADS * DIMM * DIMM];         // M_h = scale * Wq_h @ Wk_h^T
static __device__ float g_n [HEADS * DIMM * DIMM];         // N_h = Wv_h @ Wo_h (stacked rows)
static __device__ float g_qw[BTT * HEADS * NL * DIMM];     // QW per (bt,h)
static __device__ float g_s [BTT * HEADS * NL * NKV];      // scores (35.7 MB, L2-resident)
static __device__ float g_pi[BTT * NL * HEADS * DIMM];     // PI, layout [bt][r][h][128]
static __device__ float g_fp[BTT * 4 * NL * DIMM];         // split-K partials for final

// fp32 -> tf32 round-to-nearest
__device__ __forceinline__ float cf(float x){
    unsigned u; asm("cvt.rna.tf32.f32 %0, %1;" : "=r"(u) : "f"(x));
    return __uint_as_float(u);
}

__device__ __forceinline__ void mma8(float* d, const unsigned* a, const unsigned* b){
    asm volatile("mma.sync.aligned.m16n8k8.row.col.f32.tf32.tf32.f32 "
        "{%0,%1,%2,%3}, {%4,%5,%6,%7}, {%8,%9}, {%0,%1,%2,%3};"
        : "+f"(d[0]), "+f"(d[1]), "+f"(d[2]), "+f"(d[3])
        : "r"(a[0]), "r"(a[1]), "r"(a[2]), "r"(a[3]), "r"(b[0]), "r"(b[1]));
}

// ---------------------------------------------------------------------------
// tf32 MMA core (proven in Round 2): CTA 64x128, BK=32, 4 warps, warp 32x64.
// TRANSB: B given [N][K] row-major. GUARDN: B rows / C cols beyond Nrem
// zero-padded / skipped. EXPA: apply p = exp(x - mrow)*ilrow to A elements
// during staging (fused softmax; mrow/ilrow are per-A-loader-row values).
// ---------------------------------------------------------------------------
template<bool TRANSB, bool GUARDN, bool EXPA>
__device__ __forceinline__ void mma_core(
    const float* __restrict__ A, int lda,
    const float* __restrict__ B, int ldb,
    float* __restrict__ C, int ldc,
    int K, int Nrem, float alpha, float mrow, float ilrow)
{
    __shared__ float As[BK][72];
    __shared__ float Bs[BK][136];
    const int t    = threadIdx.x;
    const int warp = t >> 5, lane = t & 31;
    const int grp  = lane >> 2, qid = lane & 3;
    const int wm   = (warp & 1) * 32, wn = (warp >> 1) * 64;

    const int arow = t >> 1, ak0 = (t & 1) * 16;
    const float* Ap = A + (size_t)arow * lda + ak0;
    const int brow = t >> 2, bcol = (t & 3) * 32;
    const float* Bp;
    bool bval = true;
    if (TRANSB) { Bp = B + (size_t)t * ldb; if (GUARDN) bval = (t < Nrem); }
    else        { Bp = B + (size_t)brow * ldb + bcol; }

    float4 ar[4], br[8];
    float acc[2][8][4];
    #pragma unroll
    for (int f = 0; f < 2; f++)
        #pragma unroll
        for (int j = 0; j < 8; j++)
            #pragma unroll
            for (int i = 0; i < 4; i++) acc[f][j][i] = 0.f;

    const int nk = K / BK;

    #pragma unroll
    for (int i = 0; i < 4; i++) ar[i] = *(const float4*)(Ap + 4*i);
    if (TRANSB) {
        #pragma unroll
        for (int i = 0; i < 8; i++)
            br[i] = bval ? *(const float4*)(Bp + 4*i) : make_float4(0.f,0.f,0.f,0.f);
    } else {
        #pragma unroll
        for (int i = 0; i < 8; i++) br[i] = *(const float4*)(Bp + 4*i);
    }

    for (int c = 0; c < nk; c++) {
        #pragma unroll
        for (int i = 0; i < 4; i++) {
            float4 a = ar[i];
            if (EXPA) {
                a.x = __expf(a.x - mrow) * ilrow;
                a.y = __expf(a.y - mrow) * ilrow;
                a.z = __expf(a.z - mrow) * ilrow;
                a.w = __expf(a.w - mrow) * ilrow;
            }
            int kc = ak0 + 4*i;
            As[kc+0][arow] = cf(a.x); As[kc+1][arow] = cf(a.y);
            As[kc+2][arow] = cf(a.z); As[kc+3][arow] = cf(a.w);
        }
        if (TRANSB) {
            #pragma unroll
            for (int i = 0; i < 8; i++) {
                int kc = 4*i;
                Bs[kc+0][t] = cf(br[i].x); Bs[kc+1][t] = cf(br[i].y);
                Bs[kc+2][t] = cf(br[i].z); Bs[kc+3][t] = cf(br[i].w);
            }
        } else {
            #pragma unroll
            for (int i = 0; i < 8; i++) {
                float4 v;
                v.x = cf(br[i].x); v.y = cf(br[i].y);
                v.z = cf(br[i].z); v.w = cf(br[i].w);
                *(float4*)&Bs[brow][bcol + 4*i] = v;
            }
        }
        __syncthreads();

        if (c + 1 < nk) {
            const float* Ap2 = Ap + (c + 1) * BK;
            #pragma unroll
            for (int i = 0; i < 4; i++) ar[i] = *(const float4*)(Ap2 + 4*i);
            if (TRANSB) {
                const float* Bp2 = Bp + (c + 1) * BK;
                #pragma unroll
                for (int i = 0; i < 8; i++)
                    br[i] = bval ? *(const float4*)(Bp2 + 4*i) : make_float4(0.f,0.f,0.f,0.f);
            } else {
                const float* Bp2 = Bp + (size_t)(c + 1) * BK * ldb;
                #pragma unroll
                for (int i = 0; i < 8; i++) br[i] = *(const float4*)(Bp2 + 4*i);
            }
        }

        #pragma unroll
        for (int kk = 0; kk < BK; kk += 8) {
            unsigned a[2][4], b[8][2];
            #pragma unroll
            for (int f = 0; f < 2; f++) {
                a[f][0] = __float_as_uint(As[kk+qid  ][wm+16*f+grp  ]);
                a[f][1] = __float_as_uint(As[kk+qid  ][wm+16*f+grp+8]);
                a[f][2] = __float_as_uint(As[kk+qid+4][wm+16*f+grp  ]);
                a[f][3] = __float_as_uint(As[kk+qid+4][wm+16*f+grp+8]);
            }
            #pragma unroll
            for (int j = 0; j < 8; j++) {
                b[j][0] = __float_as_uint(Bs[kk+qid  ][wn+8*j+grp]);
                b[j][1] = __float_as_uint(Bs[kk+qid+4][wn+8*j+grp]);
            }
            #pragma unroll
            for (int f = 0; f < 2; f++)
                #pragma unroll
                for (int j = 0; j < 8; j++) mma8(acc[f][j], a[f], b[j]);
        }
        __syncthreads();
    }

    #pragma unroll
    for (int f = 0; f < 2; f++) {
        int r0 = wm + 16*f + grp;
        #pragma unroll
        for (int j = 0; j < 8; j++) {
            int col = wn + 8*j + 2*qid;
            if (GUARDN && col >= Nrem) continue;
            *(float2*)&C[(size_t)r0 * ldc + col] =
                make_float2(acc[f][j][0]*alpha, acc[f][j][1]*alpha);
            *(float2*)&C[(size_t)(r0+8) * ldc + col] =
                make_float2(acc[f][j][2]*alpha, acc[f][j][3]*alpha);
        }
    }
}

// ---------------------------------------------------------------------------
// fp32 64x64 GEMM cores (Round 1, proven) for the tiny weight precomputes
// ---------------------------------------------------------------------------
__device__ __forceinline__ void f32_nn_core(
    const float* __restrict__ A, const float* __restrict__ B, float* __restrict__ C,
    int lda, int ldb, int ldc, int K, float alpha, int m0, int n0)
{
    __shared__ float As[16][68];
    __shared__ float Bs[16][68];
    const int t  = threadIdx.x;
    const int tx = t & 15, ty = t >> 4;
    const int am = t >> 2, ak = (t & 3) << 2;
    const int bk = t >> 4, bn = (t & 15) << 2;
    const float* Ap = A + (size_t)(m0 + am) * lda + ak;
    const float* Bp = B + (size_t)bk * ldb + n0 + bn;
    float acc[4][4] = {};
    for (int kb = 0; kb < K; kb += 16) {
        float4 a = *(const float4*)(Ap + kb);
        float4 b = *(const float4*)(Bp + (size_t)kb * ldb);
        As[ak+0][am] = a.x; As[ak+1][am] = a.y; As[ak+2][am] = a.z; As[ak+3][am] = a.w;
        *(float4*)&Bs[bk][bn] = b;
        __syncthreads();
        #pragma unroll
        for (int k = 0; k < 16; ++k) {
            float4 av = *(const float4*)&As[k][ty << 2];
            float4 bv = *(const float4*)&Bs[k][tx << 2];
            acc[0][0] += av.x*bv.x; acc[0][1] += av.x*bv.y; acc[0][2] += av.x*bv.z; acc[0][3] += av.x*bv.w;
            acc[1][0] += av.y*bv.x; acc[1][1] += av.y*bv.y; acc[1][2] += av.y*bv.z; acc[1][3] += av.y*bv.w;
            acc[2][0] += av.z*bv.x; acc[2][1] += av.z*bv.y; acc[2][2] += av.z*bv.z; acc[2][3] += av.z*bv.w;
            acc[3][0] += av.w*bv.x; acc[3][1] += av.w*bv.y; acc[3][2] += av.w*bv.z; acc[3][3] += av.w*bv.w;
        }
        __syncthreads();
    }
    #pragma unroll
    for (int i = 0; i < 4; ++i) {
        float4 r;
        r.x = acc[i][0]*alpha; r.y = acc[i][1]*alpha; r.z = acc[i][2]*alpha; r.w = acc[i][3]*alpha;
        *(float4*)&C[(size_t)(m0 + (ty << 2) + i) * ldc + n0 + (tx << 2)] = r;
    }
}

__device__ __forceinline__ void f32_nt_core(
    const float* __restrict__ A, const float* __restrict__ Bm, float* __restrict__ C,
    int lda, int ldb, int ldc, int K, float alpha, int m0, int n0)
{
    __shared__ float As[16][68];
    __shared__ float Bs[16][68];
    const int t  = threadIdx.x;
    const int tx = t & 15, ty = t >> 4;
    const int am = t >> 2, ak = (t & 3) << 2;
    const int bn = t >> 2, bq = (t & 3) << 2;
    const float* Ap = A  + (size_t)(m0 + am) * lda + ak;
    const float* Bp = Bm + (size_t)(n0 + bn) * ldb + bq;
    float acc[4][4] = {};
    for (int kb = 0; kb < K; kb += 16) {
        float4 a = *(const float4*)(Ap + kb);
        float4 b = *(const float4*)(Bp + kb);
        As[ak+0][am] = a.x; As[ak+1][am] = a.y; As[ak+2][am] = a.z; As[ak+3][am] = a.w;
        Bs[bq+0][bn] = b.x; Bs[bq+1][bn] = b.y; Bs[bq+2][bn] = b.z; Bs[bq+3][bn] = b.w;
        __syncthreads();
        #pragma unroll
        for (int k = 0; k < 16; ++k) {
            float4 av = *(const float4*)&As[k][ty << 2];
            float4 bv = *(const float4*)&Bs[k][tx << 2];
            acc[0][0] += av.x*bv.x; acc[0][1] += av.x*bv.y; acc[0][2] += av.x*bv.z; acc[0][3] += av.x*bv.w;
            acc[1][0] += av.y*bv.x; acc[1][1] += av.y*bv.y; acc[1][2] += av.y*bv.z; acc[1][3] += av.y*bv.w;
            acc[2][0] += av.z*bv.x; acc[2][1] += av.z*bv.y; acc[2][2] += av.z*bv.z; acc[2][3] += av.z*bv.w;
            acc[3][0] += av.w*bv.x; acc[3][1] += av.w*bv.y; acc[3][2] += av.w*bv.z; acc[3][3] += av.w*bv.w;
        }
        __syncthreads();
    }
    #pragma unroll
    for (int i = 0; i < 4; ++i) {
        float4 r;
        r.x = acc[i][0]*alpha; r.y = acc[i][1]*alpha; r.z = acc[i][2]*alpha; r.w = acc[i][3]*alpha;
        *(float4*)&C[(size_t)(m0 + (ty << 2) + i) * ldc + n0 + (tx << 2)] = r;
    }
}

// ---------------------------------------------------------------------------
// Kernels
// ---------------------------------------------------------------------------

// concat(tensor, latents) -> g_in [BTT*NKV, 128]
__global__ void k_concat(const float* __restrict__ tensor, const float* __restrict__ latents)
{
    int idx = blockIdx.x * 256 + threadIdx.x;
    int row = idx >> 5, c4 = idx & 31;
    int bt = row / NKV, j = row - bt * NKV;
    const float* src = (j < NM)
        ? tensor  + (size_t)(bt * NM + j)        * DIMM
        : latents + (size_t)(bt * NL + (j - NM)) * DIMM;
    ((float4*)(g_in + (size_t)row * DIMM))[c4] = ((const float4*)src)[c4];
}

// M_h = QSCALE * Wq_h @ Wk_h^T : [128x256] @ [128x256]^T, fp32
__global__ void k_pre_m(const float* __restrict__ Wq, const float* __restrict__ Wkv)
{
    int h = blockIdx.z;
    f32_nt_core(Wq + h * 256, Wkv + h * 256, g_m + h * DIMM * DIMM,
                INNER, 2 * INNER, DIMM, 256, QSCALE,
                blockIdx.y * 64, blockIdx.x * 64);
}

// N_h = Wv_h @ Wo_h : [128x256] @ [256x128], fp32 (stacked into g_n rows h*128..)
__global__ void k_pre_n(const float* __restrict__ Wkv, const float* __restrict__ Wo)
{
    int h = blockIdx.z;
    f32_nn_core(Wkv + INNER + h * 256, Wo + h * 256 * DIMM, g_n + h * DIMM * DIMM,
                2 * INNER, DIMM, DIMM, 256, 1.0f,
                blockIdx.y * 64, blockIdx.x * 64);
}

// QW[z] = latents[bt] @ M_h : [64x128] @ [128x128]
__global__ void __launch_bounds__(NTHREADS) k_qw(const float* __restrict__ latents)
{
    int z = blockIdx.x, bt = z >> 3, h = z & 7;
    mma_core<false,false,false>(
        latents + (size_t)bt * NL * DIMM, DIMM,
        g_m + (size_t)h * DIMM * DIMM, DIMM,
        g_qw + (size_t)z * NL * DIMM, DIMM,
        DIMM, BN, 1.0f, 0.f, 1.f);
}

// S[z] = QW[z] @ g_in[bt]^T : [64x128] @ [1088x128]^T -> [64x1088]
__global__ void __launch_bounds__(NTHREADS) k_sim2()
{
    int z = blockIdx.z, bt = z >> 3;
    int n0 = blockIdx.x * BN;
    mma_core<true,true,false>(
        g_qw + (size_t)z * NL * DIMM, DIMM,
        g_in + ((size_t)bt * NKV + n0) * DIMM, DIMM,
        g_s + (size_t)z * NL * NKV + n0, NKV,
        DIMM, NKV - n0, 1.0f, 0.f, 1.f);
}

// PI[z] = softmax(S[z]) @ g_in[bt] : [64x1088] @ [1088x128], softmax fused
__global__ void __launch_bounds__(NTHREADS) k_pi()
{
    __shared__ float sm_m[NL], sm_il[NL];
    int z = blockIdx.x, bt = z >> 3, h = z & 7;
    const float* S = g_s + (size_t)z * NL * NKV;
    const int t = threadIdx.x, w = t >> 5, lane = t & 31;

    // pre-pass: per-row max & sum, 4 warps x 16 rows, 4-row ILP
    #pragma unroll
    for (int jb = 0; jb < 4; jb++) {
        int r0 = w * 16 + jb * 4;
        const float* p0 = S + (size_t)(r0+0) * NKV;
        const float* p1 = S + (size_t)(r0+1) * NKV;
        const float* p2 = S + (size_t)(r0+2) * NKV;
        const float* p3 = S + (size_t)(r0+3) * NKV;
        float m0=-INFINITY, m1=-INFINITY, m2=-INFINITY, m3=-INFINITY;
        for (int c = lane; c < NKV; c += 32) {
            m0 = fmaxf(m0, p0[c]); m1 = fmaxf(m1, p1[c]);
            m2 = fmaxf(m2, p2[c]); m3 = fmaxf(m3, p3[c]);
        }
        #pragma unroll
        for (int o = 16; o; o >>= 1) {
            m0 = fmaxf(m0, __shfl_xor_sync(0xffffffffu, m0, o));
            m1 = fmaxf(m1, __shfl_xor_sync(0xffffffffu, m1, o));
            m2 = fmaxf(m2, __shfl_xor_sync(0xffffffffu, m2, o));
            m3 = fmaxf(m3, __shfl_xor_sync(0xffffffffu, m3, o));
        }
        float s0=0.f, s1=0.f, s2=0.f, s3=0.f;
        for (int c = lane; c < NKV; c += 32) {
            s0 += __expf(p0[c] - m0); s1 += __expf(p1[c] - m1);
            s2 += __expf(p2[c] - m2); s3 += __expf(p3[c] - m3);
        }
        #pragma unroll
        for (int o = 16; o; o >>= 1) {
            s0 += __shfl_xor_sync(0xffffffffu, s0, o);
            s1 += __shfl_xor_sync(0xffffffffu, s1, o);
            s2 += __shfl_xor_sync(0xffffffffu, s2, o);
            s3 += __shfl_xor_sync(0xffffffffu, s3, o);
        }
        if (lane == 0) {
            sm_m[r0+0] = m0; sm_il[r0+0] = 1.0f / s0;
            sm_m[r0+1] = m1; sm_il[r0+1] = 1.0f / s1;
            sm_m[r0+2] = m2; sm_il[r0+2] = 1.0f / s2;
            sm_m[r0+3] = m3; sm_il[r0+3] = 1.0f / s3;
        }
    }
    __syncthreads();

    const int arow = t >> 1;
    float mrow = sm_m[arow], ilrow = sm_il[arow];

    mma_core<false,false,true>(
        S, NKV,
        g_in + (size_t)bt * NKV * DIMM, DIMM,
        g_pi + (size_t)bt * NL * INNER / 2 + h * DIMM, HEADS * DIMM,  // [bt][r][h][128], ldc=1024
        NKV, BN, 1.0f, mrow, ilrow);
}

// split-K partials of out[bt] = PIcat[bt] (64x1024) @ g_n (1024x128)
__global__ void __launch_bounds__(NTHREADS) k_final_part()
{
    int s = blockIdx.x, bt = blockIdx.y;
    mma_core<false,false,false>(
        g_pi + (size_t)bt * NL * (HEADS*DIMM) + s * 256, HEADS * DIMM,
        g_n + (size_t)s * 256 * DIMM, DIMM,
        g_fp + ((size_t)bt * 4 + s) * NL * DIMM, DIMM,
        256, BN, 1.0f, 0.f, 1.f);
}

// reduce 4 split-K partials -> out
__global__ void k_final_red(float* __restrict__ out)
{
    int i = blockIdx.x * 256 + threadIdx.x;        // float4 index, 32768 total
    int bt = i >> 11, inner = i & 2047;
    const float4* fp = (const float4*)g_fp;
    float4 a = fp[((size_t)bt*4 + 0) * 2048 + inner];
    float4 b = fp[((size_t)bt*4 + 1) * 2048 + inner];
    float4 c = fp[((size_t)bt*4 + 2) * 2048 + inner];
    float4 d = fp[((size_t)bt*4 + 3) * 2048 + inner];
    float4 r;
    r.x = (a.x + b.x) + (c.x + d.x);
    r.y = (a.y + b.y) + (c.y + d.y);
    r.z = (a.z + b.z) + (c.z + d.z);
    r.w = (a.w + b.w) + (c.w + d.w);
    ((float4*)out)[i] = r;
}

// ---------------------------------------------------------------------------

extern "C" void kernel_launch(void* const* d_in, const int* in_sizes, int n_in,
                              void* d_out, int out_size)
{
    const float* tensor  = (const float*)d_in[0];
    const float* latents = (const float*)d_in[1];
    const float* Wq      = (const float*)d_in[2];
    const float* Wkv     = (const float*)d_in[3];
    const float* Wo      = (const float*)d_in[4];
    float*       out     = (float*)d_out;

    (void)in_sizes; (void)n_in; (void)out_size;

    k_concat    <<<(BTT * NKV * DIMM / 4) / 256, 256>>>(tensor, latents);
    k_pre_m     <<<dim3(2, 2, HEADS), 256>>>(Wq, Wkv);
    k_pre_n     <<<dim3(2, 2, HEADS), 256>>>(Wkv, Wo);
    k_qw        <<<BTT * HEADS, NTHREADS>>>(latents);
    k_sim2      <<<dim3((NKV + BN - 1) / BN, 1, BTT * HEADS), NTHREADS>>>();
    k_pi        <<<BTT * HEADS, NTHREADS>>>();
    k_final_part<<<dim3(4, BTT), NTHREADS>>>();
    k_final_red <<<(BTT * NL * DIMM / 4) / 256, 256>>>(out);
}

// round 4
// speedup vs baseline: 6.3167x; 1.2259x over previous
#include <cuda_runtime.h>
#include <math.h>

// Problem constants
#define BTT     16
#define NM      1024
#define NL      64
#define NKV     1088
#define DIMM    128
#define HEADS   8
#define INNER   2048
#define QSCALE  0.08838834764831845f   // 128^-0.5

// Static device scratch
static __device__ float g_in[BTT * NKV * DIMM];            // 8.9 MB concat(tensor, latents)
static __device__ float g_m [HEADS * DIMM * DIMM];         // M_h = scale * Wq_h @ Wk_h^T
static __device__ float g_n [HEADS * DIMM * DIMM];         // N_h = Wv_h @ Wo_h
static __device__ float g_pi[BTT * NL * HEADS * DIMM];     // PI [bt][r][h][128]
static __device__ float g_fp[BTT * 4 * NL * DIMM];         // split-K partials

// fp32 -> tf32 round-to-nearest
__device__ __forceinline__ float cf(float x){
    unsigned u; asm("cvt.rna.tf32.f32 %0, %1;" : "=r"(u) : "f"(x));
    return __uint_as_float(u);
}

__device__ __forceinline__ void mma8(float* d, const unsigned* a, const unsigned* b){
    asm volatile("mma.sync.aligned.m16n8k8.row.col.f32.tf32.tf32.f32 "
        "{%0,%1,%2,%3}, {%4,%5,%6,%7}, {%8,%9}, {%0,%1,%2,%3};"
        : "+f"(d[0]), "+f"(d[1]), "+f"(d[2]), "+f"(d[3])
        : "r"(a[0]), "r"(a[1]), "r"(a[2]), "r"(a[3]), "r"(b[0]), "r"(b[1]));
}

// ===========================================================================
// Flash kernel building blocks: 256 threads (8 warps), CTA tile 64x128,
// warp tile 16x64. A resident in smem as At[k][72] (tf32), B staged per
// BK=32 chunk into Bs[32][136] with register prefetch.
// ===========================================================================

__device__ __forceinline__ void frag_compute(
    const float* __restrict__ At, const float* __restrict__ Bs,
    float acc[8][4], int wm, int wn, int grp, int qid, int kbase)
{
    #pragma unroll
    for (int kk = 0; kk < 32; kk += 8) {
        unsigned a[4], b[8][2];
        const int k0 = kbase + kk;
        a[0] = __float_as_uint(At[(k0+qid  )*72 + wm+grp  ]);
        a[1] = __float_as_uint(At[(k0+qid  )*72 + wm+grp+8]);
        a[2] = __float_as_uint(At[(k0+qid+4)*72 + wm+grp  ]);
        a[3] = __float_as_uint(At[(k0+qid+4)*72 + wm+grp+8]);
        #pragma unroll
        for (int j = 0; j < 8; j++) {
            b[j][0] = __float_as_uint(Bs[(kk+qid  )*136 + wn+8*j+grp]);
            b[j][1] = __float_as_uint(Bs[(kk+qid+4)*136 + wn+8*j+grp]);
        }
        #pragma unroll
        for (int j = 0; j < 8; j++) mma8(acc[j], a, b[j]);
    }
}

// NN: B[k][n] global, ldb = row stride. K multiple of 32.
__device__ __forceinline__ void gemm_nn_sA(
    const float* __restrict__ At, const float* __restrict__ Bg, int ldb, int K,
    float acc[8][4], float* __restrict__ Bs,
    int wm, int wn, int grp, int qid, int t)
{
    const int br = t >> 3, bc = (t & 7) * 16;
    const float* Bp = Bg + (size_t)br * ldb + bc;
    float4 pre[4];
    #pragma unroll
    for (int i = 0; i < 4; i++) pre[i] = *(const float4*)(Bp + 4*i);
    for (int c = 0; c < K; c += 32) {
        __syncthreads();
        #pragma unroll
        for (int i = 0; i < 4; i++) {
            float4 v;
            v.x = cf(pre[i].x); v.y = cf(pre[i].y);
            v.z = cf(pre[i].z); v.w = cf(pre[i].w);
            *(float4*)&Bs[br*136 + bc + 4*i] = v;
        }
        __syncthreads();
        if (c + 32 < K) {
            const float* Bp2 = Bp + (size_t)(c + 32) * ldb;
            #pragma unroll
            for (int i = 0; i < 4; i++) pre[i] = *(const float4*)(Bp2 + 4*i);
        }
        frag_compute(At, Bs, acc, wm, wn, grp, qid, c);
    }
}

// TRANSB: B[n][k] global (rows = output-n = kv). Rows >= validN zero-padded.
__device__ __forceinline__ void gemm_tb_sA(
    const float* __restrict__ At, const float* __restrict__ Bg, int ldb, int K,
    int validN, float acc[8][4], float* __restrict__ Bs,
    int wm, int wn, int grp, int qid, int t)
{
    const int bn = t >> 1, bk0 = (t & 1) * 16;
    const bool v = bn < validN;
    const float* Bp = Bg + (size_t)bn * ldb + bk0;
    float4 pre[4];
    #pragma unroll
    for (int i = 0; i < 4; i++)
        pre[i] = v ? *(const float4*)(Bp + 4*i) : make_float4(0.f,0.f,0.f,0.f);
    for (int c = 0; c < K; c += 32) {
        __syncthreads();
        #pragma unroll
        for (int i = 0; i < 4; i++) {
            const int k = bk0 + 4*i;
            Bs[(k+0)*136 + bn] = cf(pre[i].x);
            Bs[(k+1)*136 + bn] = cf(pre[i].y);
            Bs[(k+2)*136 + bn] = cf(pre[i].z);
            Bs[(k+3)*136 + bn] = cf(pre[i].w);
        }
        __syncthreads();
        if (c + 32 < K) {
            #pragma unroll
            for (int i = 0; i < 4; i++)
                pre[i] = v ? *(const float4*)(Bp + (c + 32) + 4*i)
                           : make_float4(0.f,0.f,0.f,0.f);
        }
        frag_compute(At, Bs, acc, wm, wn, grp, qid, c);
    }
}

// ===========================================================================
// k_flash: per (bt,h) fused  QW = lat@M_h ; loop kv blocks:
//   S = QW@in^T ; online softmax ; O += P@in ; finally PI = O/l
// ===========================================================================
__global__ void __launch_bounds__(256) k_flash(const float* __restrict__ latents)
{
    extern __shared__ float sm[];
    float* QWt   = sm;                    // [128][72]
    float* SXt   = sm + 128*72;           // lat staging, then S/P [128][72]
    float* Bs    = sm + 2*128*72;         // [32][136]
    float* m_run = Bs + 32*136;           // [64]
    float* l_run = m_run + 64;            // [64]
    float* rsc   = l_run + 64;            // [64]

    const int z = blockIdx.x, bt = z >> 3, h = z & 7;
    const int t = threadIdx.x, warp = t >> 5, lane = t & 31;
    const int grp = lane >> 2, qid = lane & 3;
    const int wm = (warp & 3) * 16, wn = (warp >> 2) * 64;

    if (t < 64) { m_run[t] = -INFINITY; l_run[t] = 0.f; }

    // stage latents[bt] (64x128) transposed -> SXt[k][r]
    {
        const float* Lp = latents + (size_t)bt * NL * DIMM + (t >> 2) * DIMM + (t & 3) * 32;
        const int r = t >> 2, k0 = (t & 3) * 32;
        #pragma unroll
        for (int i = 0; i < 8; i++) {
            float4 v = *(const float4*)(Lp + 4*i);
            const int k = k0 + 4*i;
            SXt[(k+0)*72 + r] = cf(v.x);
            SXt[(k+1)*72 + r] = cf(v.y);
            SXt[(k+2)*72 + r] = cf(v.z);
            SXt[(k+3)*72 + r] = cf(v.w);
        }
    }
    __syncthreads();

    // QW = lat @ M_h  (A = SXt, K = 128)
    {
        float qacc[8][4];
        #pragma unroll
        for (int j = 0; j < 8; j++)
            #pragma unroll
            for (int i = 0; i < 4; i++) qacc[j][i] = 0.f;
        gemm_nn_sA(SXt, g_m + (size_t)h * DIMM * DIMM, DIMM, DIMM,
                   qacc, Bs, wm, wn, grp, qid, t);
        // epilogue -> QWt[col][row] (tf32)
        #pragma unroll
        for (int j = 0; j < 8; j++) {
            const int c = wn + 8*j + 2*qid;
            QWt[(c  )*72 + wm+grp  ] = cf(qacc[j][0]);
            QWt[(c+1)*72 + wm+grp  ] = cf(qacc[j][1]);
            QWt[(c  )*72 + wm+grp+8] = cf(qacc[j][2]);
            QWt[(c+1)*72 + wm+grp+8] = cf(qacc[j][3]);
        }
    }
    __syncthreads();

    float O[8][4];
    #pragma unroll
    for (int j = 0; j < 8; j++)
        #pragma unroll
        for (int i = 0; i < 4; i++) O[j][i] = 0.f;

    const float* inb = g_in + (size_t)bt * NKV * DIMM;

    for (int kv0 = 0; kv0 < NKV; kv0 += 128) {
        const int valid = (NKV - kv0 < 128) ? (NKV - kv0) : 128;   // 128 or 64

        // S block = QW @ in_blk^T  -> SXt[kv][row]
        float sacc[8][4];
        #pragma unroll
        for (int j = 0; j < 8; j++)
            #pragma unroll
            for (int i = 0; i < 4; i++) sacc[j][i] = 0.f;
        gemm_tb_sA(QWt, inb + (size_t)kv0 * DIMM, DIMM, DIMM, valid,
                   sacc, Bs, wm, wn, grp, qid, t);
        #pragma unroll
        for (int j = 0; j < 8; j++) {
            const int c = wn + 8*j + 2*qid;
            if (c < valid) {
                SXt[(c  )*72 + wm+grp  ] = sacc[j][0];
                SXt[(c  )*72 + wm+grp+8] = sacc[j][2];
            }
            if (c + 1 < valid) {
                SXt[(c+1)*72 + wm+grp  ] = sacc[j][1];
                SXt[(c+1)*72 + wm+grp+8] = sacc[j][3];
            }
        }
        __syncthreads();

        // online softmax: 4 threads per row, 32 kv each
        {
            const int row = t >> 2, part = t & 3;
            const float mo = m_run[row];
            float mx = mo;
            #pragma unroll 8
            for (int i = 0; i < 32; i++) {
                const int c = part * 32 + i;
                if (c < valid) mx = fmaxf(mx, SXt[c*72 + row]);
            }
            mx = fmaxf(mx, __shfl_xor_sync(0xffffffffu, mx, 1));
            mx = fmaxf(mx, __shfl_xor_sync(0xffffffffu, mx, 2));
            float s = 0.f;
            #pragma unroll 8
            for (int i = 0; i < 32; i++) {
                const int c = part * 32 + i;
                if (c < valid) {
                    const float e = __expf(SXt[c*72 + row] - mx);
                    SXt[c*72 + row] = cf(e);
                    s += e;
                }
            }
            s += __shfl_xor_sync(0xffffffffu, s, 1);
            s += __shfl_xor_sync(0xffffffffu, s, 2);
            if (part == 0) {
                const float scale = __expf(mo - mx);
                l_run[row] = l_run[row] * scale + s;
                m_run[row] = mx;
                rsc[row]   = scale;
            }
        }
        __syncthreads();

        // rescale O, then O += P @ in_blk  (K = valid)
        {
            const float s0 = rsc[wm+grp], s1 = rsc[wm+grp+8];
            #pragma unroll
            for (int j = 0; j < 8; j++) {
                O[j][0] *= s0; O[j][1] *= s0;
                O[j][2] *= s1; O[j][3] *= s1;
            }
        }
        gemm_nn_sA(SXt, inb + (size_t)kv0 * DIMM, DIMM, valid,
                   O, Bs, wm, wn, grp, qid, t);
        __syncthreads();
    }

    // PI = O / l -> g_pi[bt][row][h*128 + col]
    const float il0 = 1.0f / l_run[wm+grp];
    const float il1 = 1.0f / l_run[wm+grp+8];
    float* P = g_pi + (size_t)bt * NL * (HEADS*DIMM) + h * DIMM;
    #pragma unroll
    for (int j = 0; j < 8; j++) {
        const int c = wn + 8*j + 2*qid;
        *(float2*)&P[(size_t)(wm+grp  ) * (HEADS*DIMM) + c] =
            make_float2(O[j][0]*il0, O[j][1]*il0);
        *(float2*)&P[(size_t)(wm+grp+8) * (HEADS*DIMM) + c] =
            make_float2(O[j][2]*il1, O[j][3]*il1);
    }
}

// ===========================================================================
// fp32 64x64 cores for the tiny weight precomputes (256 threads)
// ===========================================================================
__device__ __forceinline__ void f32_nn_core(
    const float* __restrict__ A, const float* __restrict__ B, float* __restrict__ C,
    int lda, int ldb, int ldc, int K, float alpha, int m0, int n0)
{
    __shared__ float As[16][68];
    __shared__ float Bs[16][68];
    const int t  = threadIdx.x;
    const int tx = t & 15, ty = t >> 4;
    const int am = t >> 2, ak = (t & 3) << 2;
    const int bk = t >> 4, bn = (t & 15) << 2;
    const float* Ap = A + (size_t)(m0 + am) * lda + ak;
    const float* Bp = B + (size_t)bk * ldb + n0 + bn;
    float acc[4][4] = {};
    for (int kb = 0; kb < K; kb += 16) {
        float4 a = *(const float4*)(Ap + kb);
        float4 b = *(const float4*)(Bp + (size_t)kb * ldb);
        As[ak+0][am] = a.x; As[ak+1][am] = a.y; As[ak+2][am] = a.z; As[ak+3][am] = a.w;
        *(float4*)&Bs[bk][bn] = b;
        __syncthreads();
        #pragma unroll
        for (int k = 0; k < 16; ++k) {
            float4 av = *(const float4*)&As[k][ty << 2];
            float4 bv = *(const float4*)&Bs[k][tx << 2];
            acc[0][0] += av.x*bv.x; acc[0][1] += av.x*bv.y; acc[0][2] += av.x*bv.z; acc[0][3] += av.x*bv.w;
            acc[1][0] += av.y*bv.x; acc[1][1] += av.y*bv.y; acc[1][2] += av.y*bv.z; acc[1][3] += av.y*bv.w;
            acc[2][0] += av.z*bv.x; acc[2][1] += av.z*bv.y; acc[2][2] += av.z*bv.z; acc[2][3] += av.z*bv.w;
            acc[3][0] += av.w*bv.x; acc[3][1] += av.w*bv.y; acc[3][2] += av.w*bv.z; acc[3][3] += av.w*bv.w;
        }
        __syncthreads();
    }
    #pragma unroll
    for (int i = 0; i < 4; ++i) {
        float4 r;
        r.x = acc[i][0]*alpha; r.y = acc[i][1]*alpha; r.z = acc[i][2]*alpha; r.w = acc[i][3]*alpha;
        *(float4*)&C[(size_t)(m0 + (ty << 2) + i) * ldc + n0 + (tx << 2)] = r;
    }
}

__device__ __forceinline__ void f32_nt_core(
    const float* __restrict__ A, const float* __restrict__ Bm, float* __restrict__ C,
    int lda, int ldb, int ldc, int K, float alpha, int m0, int n0)
{
    __shared__ float As[16][68];
    __shared__ float Bs[16][68];
    const int t  = threadIdx.x;
    const int tx = t & 15, ty = t >> 4;
    const int am = t >> 2, ak = (t & 3) << 2;
    const int bn = t >> 2, bq = (t & 3) << 2;
    const float* Ap = A  + (size_t)(m0 + am) * lda + ak;
    const float* Bp = Bm + (size_t)(n0 + bn) * ldb + bq;
    float acc[4][4] = {};
    for (int kb = 0; kb < K; kb += 16) {
        float4 a = *(const float4*)(Ap + kb);
        float4 b = *(const float4*)(Bp + kb);
        As[ak+0][am] = a.x; As[ak+1][am] = a.y; As[ak+2][am] = a.z; As[ak+3][am] = a.w;
        Bs[bq+0][bn] = b.x; Bs[bq+1][bn] = b.y; Bs[bq+2][bn] = b.z; Bs[bq+3][bn] = b.w;
        __syncthreads();
        #pragma unroll
        for (int k = 0; k < 16; ++k) {
            float4 av = *(const float4*)&As[k][ty << 2];
            float4 bv = *(const float4*)&Bs[k][tx << 2];
            acc[0][0] += av.x*bv.x; acc[0][1] += av.x*bv.y; acc[0][2] += av.x*bv.z; acc[0][3] += av.x*bv.w;
            acc[1][0] += av.y*bv.x; acc[1][1] += av.y*bv.y; acc[1][2] += av.y*bv.z; acc[1][3] += av.y*bv.w;
            acc[2][0] += av.z*bv.x; acc[2][1] += av.z*bv.y; acc[2][2] += av.z*bv.z; acc[2][3] += av.z*bv.w;
            acc[3][0] += av.w*bv.x; acc[3][1] += av.w*bv.y; acc[3][2] += av.w*bv.z; acc[3][3] += av.w*bv.w;
        }
        __syncthreads();
    }
    #pragma unroll
    for (int i = 0; i < 4; ++i) {
        float4 r;
        r.x = acc[i][0]*alpha; r.y = acc[i][1]*alpha; r.z = acc[i][2]*alpha; r.w = acc[i][3]*alpha;
        *(float4*)&C[(size_t)(m0 + (ty << 2) + i) * ldc + n0 + (tx << 2)] = r;
    }
}

// ===========================================================================
// k_prep: concat (blocks 0..2175) + pre_m (2176..2207) + pre_n (2208..2239)
// ===========================================================================
#define CONCAT_BLOCKS 2176

__global__ void k_prep(const float* __restrict__ tensor, const float* __restrict__ latents,
                       const float* __restrict__ Wq, const float* __restrict__ Wkv,
                       const float* __restrict__ Wo)
{
    const int b = blockIdx.x;
    if (b < CONCAT_BLOCKS) {
        int idx = b * 256 + threadIdx.x;        // float4 index
        int row = idx >> 5, c4 = idx & 31;
        int bt = row / NKV, j = row - bt * NKV;
        const float* src = (j < NM)
            ? tensor  + (size_t)(bt * NM + j)        * DIMM
            : latents + (size_t)(bt * NL + (j - NM)) * DIMM;
        ((float4*)(g_in + (size_t)row * DIMM))[c4] = ((const float4*)src)[c4];
    } else if (b < CONCAT_BLOCKS + 32) {
        int idx = b - CONCAT_BLOCKS;
        int h = idx >> 2, sub = idx & 3;
        f32_nt_core(Wq + h * 256, Wkv + h * 256, g_m + (size_t)h * DIMM * DIMM,
                    INNER, 2 * INNER, DIMM, 256, QSCALE,
                    (sub >> 1) * 64, (sub & 1) * 64);
    } else {
        int idx = b - CONCAT_BLOCKS - 32;
        int h = idx >> 2, sub = idx & 3;
        f32_nn_core(Wkv + INNER + h * 256, Wo + (size_t)h * 256 * DIMM,
                    g_n + (size_t)h * DIMM * DIMM,
                    2 * INNER, DIMM, DIMM, 256, 1.0f,
                    (sub >> 1) * 64, (sub & 1) * 64);
    }
}

// ===========================================================================
// Final projection: split-K(4) tf32 GEMM (128 threads, R3-proven core) + reduce
// ===========================================================================
__global__ void __launch_bounds__(128) k_final_part()
{
    __shared__ float As[32][72];
    __shared__ float Bs[32][136];
    const int s = blockIdx.x, bt = blockIdx.y;
    const float* A = g_pi + (size_t)bt * NL * (HEADS*DIMM) + s * 256;   // lda = 1024
    const float* B = g_n + (size_t)s * 256 * DIMM;                      // ldb = 128
    float*       C = g_fp + ((size_t)bt * 4 + s) * NL * DIMM;           // ldc = 128
    const int lda = HEADS * DIMM, ldb = DIMM, ldc = DIMM;

    const int t    = threadIdx.x;
    const int warp = t >> 5, lane = t & 31;
    const int grp  = lane >> 2, qid = lane & 3;
    const int wm   = (warp & 1) * 32, wn = (warp >> 1) * 64;

    const int arow = t >> 1, ak0 = (t & 1) * 16;
    const float* Ap = A + (size_t)arow * lda + ak0;
    const int brow = t >> 2, bcol = (t & 3) * 32;
    const float* Bp = B + (size_t)brow * ldb + bcol;

    float4 ar[4], br[8];
    float acc[2][8][4];
    #pragma unroll
    for (int f = 0; f < 2; f++)
        #pragma unroll
        for (int j = 0; j < 8; j++)
            #pragma unroll
            for (int i = 0; i < 4; i++) acc[f][j][i] = 0.f;

    const int nk = 256 / 32;
    #pragma unroll
    for (int i = 0; i < 4; i++) ar[i] = *(const float4*)(Ap + 4*i);
    #pragma unroll
    for (int i = 0; i < 8; i++) br[i] = *(const float4*)(Bp + 4*i);

    for (int c = 0; c < nk; c++) {
        #pragma unroll
        for (int i = 0; i < 4; i++) {
            int kc = ak0 + 4*i;
            As[kc+0][arow] = cf(ar[i].x); As[kc+1][arow] = cf(ar[i].y);
            As[kc+2][arow] = cf(ar[i].z); As[kc+3][arow] = cf(ar[i].w);
        }
        #pragma unroll
        for (int i = 0; i < 8; i++) {
            float4 v;
            v.x = cf(br[i].x); v.y = cf(br[i].y);
            v.z = cf(br[i].z); v.w = cf(br[i].w);
            *(float4*)&Bs[brow][bcol + 4*i] = v;
        }
        __syncthreads();
        if (c + 1 < nk) {
            const float* Ap2 = Ap + (c + 1) * 32;
            #pragma unroll
            for (int i = 0; i < 4; i++) ar[i] = *(const float4*)(Ap2 + 4*i);
            const float* Bp2 = Bp + (size_t)(c + 1) * 32 * ldb;
            #pragma unroll
            for (int i = 0; i < 8; i++) br[i] = *(const float4*)(Bp2 + 4*i);
        }
        #pragma unroll
        for (int kk = 0; kk < 32; kk += 8) {
            unsigned a[2][4], b[8][2];
            #pragma unroll
            for (int f = 0; f < 2; f++) {
                a[f][0] = __float_as_uint(As[kk+qid  ][wm+16*f+grp  ]);
                a[f][1] = __float_as_uint(As[kk+qid  ][wm+16*f+grp+8]);
                a[f][2] = __float_as_uint(As[kk+qid+4][wm+16*f+grp  ]);
                a[f][3] = __float_as_uint(As[kk+qid+4][wm+16*f+grp+8]);
            }
            #pragma unroll
            for (int j = 0; j < 8; j++) {
                b[j][0] = __float_as_uint(Bs[kk+qid  ][wn+8*j+grp]);
                b[j][1] = __float_as_uint(Bs[kk+qid+4][wn+8*j+grp]);
            }
            #pragma unroll
            for (int f = 0; f < 2; f++)
                #pragma unroll
                for (int j = 0; j < 8; j++) mma8(acc[f][j], a[f], b[j]);
        }
        __syncthreads();
    }
    #pragma unroll
    for (int f = 0; f < 2; f++) {
        int r0 = wm + 16*f + grp;
        #pragma unroll
        for (int j = 0; j < 8; j++) {
            int col = wn + 8*j + 2*qid;
            *(float2*)&C[(size_t)r0 * ldc + col] = make_float2(acc[f][j][0], acc[f][j][1]);
            *(float2*)&C[(size_t)(r0+8) * ldc + col] = make_float2(acc[f][j][2], acc[f][j][3]);
        }
    }
}

__global__ void k_final_red(float* __restrict__ out)
{
    int i = blockIdx.x * 256 + threadIdx.x;        // float4 index, 32768 total
    int bt = i >> 11, inner = i & 2047;
    const float4* fp = (const float4*)g_fp;
    float4 a = fp[((size_t)bt*4 + 0) * 2048 + inner];
    float4 b = fp[((size_t)bt*4 + 1) * 2048 + inner];
    float4 c = fp[((size_t)bt*4 + 2) * 2048 + inner];
    float4 d = fp[((size_t)bt*4 + 3) * 2048 + inner];
    float4 r;
    r.x = (a.x + b.x) + (c.x + d.x);
    r.y = (a.y + b.y) + (c.y + d.y);
    r.z = (a.z + b.z) + (c.z + d.z);
    r.w = (a.w + b.w) + (c.w + d.w);
    ((float4*)out)[i] = r;
}

// ---------------------------------------------------------------------------

#define FLASH_SMEM ((2*128*72 + 32*136 + 3*64) * 4)

extern "C" void kernel_launch(void* const* d_in, const int* in_sizes, int n_in,
                              void* d_out, int out_size)
{
    const float* tensor  = (const float*)d_in[0];
    const float* latents = (const float*)d_in[1];
    const float* Wq      = (const float*)d_in[2];
    const float* Wkv     = (const float*)d_in[3];
    const float* Wo      = (const float*)d_in[4];
    float*       out     = (float*)d_out;

    (void)in_sizes; (void)n_in; (void)out_size;

    cudaFuncSetAttribute(k_flash, cudaFuncAttributeMaxDynamicSharedMemorySize, FLASH_SMEM);

    k_prep      <<<CONCAT_BLOCKS + 64, 256>>>(tensor, latents, Wq, Wkv, Wo);
    k_flash     <<<BTT * HEADS, 256, FLASH_SMEM>>>(latents);
    k_final_part<<<dim3(4, BTT), 128>>>();
    k_final_red <<<(BTT * NL * DIMM / 4) / 256, 256>>>(out);
}

// round 5
// speedup vs baseline: 7.0269x; 1.1124x over previous
#include <cuda_runtime.h>
#include <math.h>

// Problem constants
#define BTT     16
#define NM      1024
#define NL      64
#define NKV     1088
#define DIMM    128
#define HEADS   8
#define INNER   2048
#define QSCALE  0.08838834764831845f   // 128^-0.5
#define KVHALF  544

// Static device scratch
static __device__ float  g_m  [HEADS * DIMM * DIMM];          // M_h = scale*Wq_h@Wk_h^T
static __device__ float  g_n  [HEADS * DIMM * DIMM];          // N_h = Wv_h@Wo_h
static __device__ float  g_po [2 * BTT * HEADS * NL * DIMM];  // un-normalized O halves
static __device__ float2 g_ml2[2 * BTT * HEADS * NL];         // (m, l) per half per row
static __device__ float  g_fp [BTT * HEADS * NL * DIMM];      // per-head partials of out

// fp32 -> tf32 round-to-nearest
__device__ __forceinline__ float cf(float x){
    unsigned u; asm("cvt.rna.tf32.f32 %0, %1;" : "=r"(u) : "f"(x));
    return __uint_as_float(u);
}

__device__ __forceinline__ void mma8(float* d, const unsigned* a, const unsigned* b){
    asm volatile("mma.sync.aligned.m16n8k8.row.col.f32.tf32.tf32.f32 "
        "{%0,%1,%2,%3}, {%4,%5,%6,%7}, {%8,%9}, {%0,%1,%2,%3};"
        : "+f"(d[0]), "+f"(d[1]), "+f"(d[2]), "+f"(d[3])
        : "r"(a[0]), "r"(a[1]), "r"(a[2]), "r"(a[3]), "r"(b[0]), "r"(b[1]));
}

// row r of concat(tensor[bt], latents[bt]) without materializing it
__device__ __forceinline__ const float* row_ptr(
    const float* __restrict__ tensor, const float* __restrict__ latents, int bt, int r)
{
    return (r < NM) ? tensor  + ((size_t)bt * NM + r)        * DIMM
                    : latents + ((size_t)bt * NL + (r - NM)) * DIMM;
}

// ===========================================================================
// Flash building blocks: 256 threads (8 warps), warp tile 16x64.
// A resident in smem At[k][72] (tf32). B staged per BK=32 into Bs[32][136].
// ===========================================================================

__device__ __forceinline__ void frag_compute(
    const float* __restrict__ At, const float* __restrict__ Bs,
    float acc[8][4], int wm, int wn, int grp, int qid, int kbase)
{
    #pragma unroll
    for (int kk = 0; kk < 32; kk += 8) {
        unsigned a[4], b[8][2];
        const int k0 = kbase + kk;
        a[0] = __float_as_uint(At[(k0+qid  )*72 + wm+grp  ]);
        a[1] = __float_as_uint(At[(k0+qid  )*72 + wm+grp+8]);
        a[2] = __float_as_uint(At[(k0+qid+4)*72 + wm+grp  ]);
        a[3] = __float_as_uint(At[(k0+qid+4)*72 + wm+grp+8]);
        #pragma unroll
        for (int j = 0; j < 8; j++) {
            b[j][0] = __float_as_uint(Bs[(kk+qid  )*136 + wn+8*j+grp]);
            b[j][1] = __float_as_uint(Bs[(kk+qid+4)*136 + wn+8*j+grp]);
        }
        #pragma unroll
        for (int j = 0; j < 8; j++) mma8(acc[j], a, b[j]);
    }
}

// NN with contiguous weight B[k][n] (ldb row stride), K multiple of 32
__device__ __forceinline__ void gemm_w(
    const float* __restrict__ At, const float* __restrict__ Bg, int ldb, int K,
    float acc[8][4], float* __restrict__ Bs,
    int wm, int wn, int grp, int qid, int t)
{
    const int br = t >> 3, bc = (t & 7) * 16;
    const float* Bp = Bg + (size_t)br * ldb + bc;
    float4 pre[4];
    #pragma unroll
    for (int i = 0; i < 4; i++) pre[i] = *(const float4*)(Bp + 4*i);
    for (int c = 0; c < K; c += 32) {
        __syncthreads();
        #pragma unroll
        for (int i = 0; i < 4; i++) {
            float4 v;
            v.x = cf(pre[i].x); v.y = cf(pre[i].y);
            v.z = cf(pre[i].z); v.w = cf(pre[i].w);
            *(float4*)&Bs[br*136 + bc + 4*i] = v;
        }
        __syncthreads();
        if (c + 32 < K) {
            const float* Bp2 = Bp + (size_t)(c + 32) * ldb;
            #pragma unroll
            for (int i = 0; i < 4; i++) pre[i] = *(const float4*)(Bp2 + 4*i);
        }
        frag_compute(At, Bs, acc, wm, wn, grp, qid, c);
    }
}

// TRANSB over in-rows: B row = concat row (row0 + bn), K = 128 (dim)
__device__ __forceinline__ void gemm_tb_in(
    const float* __restrict__ At,
    const float* __restrict__ tensor, const float* __restrict__ latents,
    int bt, int row0, int validN, float acc[8][4], float* __restrict__ Bs,
    int wm, int wn, int grp, int qid, int t)
{
    const int bn = t >> 1, bk0 = (t & 1) * 16;
    const bool v = bn < validN;
    const float* Bp = row_ptr(tensor, latents, bt, row0 + (v ? bn : 0)) + bk0;
    float4 pre[4];
    #pragma unroll
    for (int i = 0; i < 4; i++)
        pre[i] = v ? *(const float4*)(Bp + 4*i) : make_float4(0.f,0.f,0.f,0.f);
    for (int c = 0; c < DIMM; c += 32) {
        __syncthreads();
        #pragma unroll
        for (int i = 0; i < 4; i++) {
            const int k = bk0 + 4*i;
            Bs[(k+0)*136 + bn] = cf(pre[i].x);
            Bs[(k+1)*136 + bn] = cf(pre[i].y);
            Bs[(k+2)*136 + bn] = cf(pre[i].z);
            Bs[(k+3)*136 + bn] = cf(pre[i].w);
        }
        __syncthreads();
        if (c + 32 < DIMM) {
            #pragma unroll
            for (int i = 0; i < 4; i++)
                pre[i] = v ? *(const float4*)(Bp + (c + 32) + 4*i)
                           : make_float4(0.f,0.f,0.f,0.f);
        }
        frag_compute(At, Bs, acc, wm, wn, grp, qid, c);
    }
}

// NN over in-rows: B row = concat row (row0 + c + br), K = kv count (mult of 32)
__device__ __forceinline__ void gemm_nn_in(
    const float* __restrict__ At,
    const float* __restrict__ tensor, const float* __restrict__ latents,
    int bt, int row0, int K, float acc[8][4], float* __restrict__ Bs,
    int wm, int wn, int grp, int qid, int t)
{
    const int br = t >> 3, bc = (t & 7) * 16;
    float4 pre[4];
    {
        const float* Bp = row_ptr(tensor, latents, bt, row0 + br) + bc;
        #pragma unroll
        for (int i = 0; i < 4; i++) pre[i] = *(const float4*)(Bp + 4*i);
    }
    for (int c = 0; c < K; c += 32) {
        __syncthreads();
        #pragma unroll
        for (int i = 0; i < 4; i++) {
            float4 v;
            v.x = cf(pre[i].x); v.y = cf(pre[i].y);
            v.z = cf(pre[i].z); v.w = cf(pre[i].w);
            *(float4*)&Bs[br*136 + bc + 4*i] = v;
        }
        __syncthreads();
        if (c + 32 < K) {
            const float* Bp2 = row_ptr(tensor, latents, bt, row0 + c + 32 + br) + bc;
            #pragma unroll
            for (int i = 0; i < 4; i++) pre[i] = *(const float4*)(Bp2 + 4*i);
        }
        frag_compute(At, Bs, acc, wm, wn, grp, qid, c);
    }
}

// ===========================================================================
// k_flash: grid 256 = (bt,h,half). Per CTA: QW = lat@M_h, then loop over
// this half's KV (544) in blocks of 128: S = QW@in^T, online softmax,
// O += P@in. Stores un-normalized O and (m,l).
// ===========================================================================
__global__ void __launch_bounds__(256, 2) k_flash(
    const float* __restrict__ tensor, const float* __restrict__ latents)
{
    extern __shared__ float sm[];
    float* QWt   = sm;                    // [128][72]
    float* SXt   = sm + 128*72;           // staging / S / P [128][72]
    float* Bs    = sm + 2*128*72;         // [32][136]
    float* m_run = Bs + 32*136;           // [64]
    float* l_run = m_run + 64;            // [64]
    float* rsc   = l_run + 64;            // [64]

    const int zz = blockIdx.x;            // 0..255
    const int z = zz >> 1, half = zz & 1;
    const int bt = z >> 3, h = z & 7;
    const int kvbase = half * KVHALF;

    const int t = threadIdx.x, warp = t >> 5, lane = t & 31;
    const int grp = lane >> 2, qid = lane & 3;
    const int wm = (warp & 3) * 16, wn = (warp >> 2) * 64;

    if (t < 64) { m_run[t] = -INFINITY; l_run[t] = 0.f; }

    // stage latents[bt] (64x128) transposed -> SXt[k][r]
    {
        const int r = t >> 2, k0 = (t & 3) * 32;
        const float* Lp = latents + (size_t)bt * NL * DIMM + (size_t)r * DIMM + k0;
        #pragma unroll
        for (int i = 0; i < 8; i++) {
            float4 v = *(const float4*)(Lp + 4*i);
            const int k = k0 + 4*i;
            SXt[(k+0)*72 + r] = cf(v.x);
            SXt[(k+1)*72 + r] = cf(v.y);
            SXt[(k+2)*72 + r] = cf(v.z);
            SXt[(k+3)*72 + r] = cf(v.w);
        }
    }
    __syncthreads();

    // QW = lat @ M_h
    {
        float qacc[8][4];
        #pragma unroll
        for (int j = 0; j < 8; j++)
            #pragma unroll
            for (int i = 0; i < 4; i++) qacc[j][i] = 0.f;
        gemm_w(SXt, g_m + (size_t)h * DIMM * DIMM, DIMM, DIMM,
               qacc, Bs, wm, wn, grp, qid, t);
        #pragma unroll
        for (int j = 0; j < 8; j++) {
            const int c = wn + 8*j + 2*qid;
            QWt[(c  )*72 + wm+grp  ] = cf(qacc[j][0]);
            QWt[(c+1)*72 + wm+grp  ] = cf(qacc[j][1]);
            QWt[(c  )*72 + wm+grp+8] = cf(qacc[j][2]);
            QWt[(c+1)*72 + wm+grp+8] = cf(qacc[j][3]);
        }
    }
    __syncthreads();

    float O[8][4];
    #pragma unroll
    for (int j = 0; j < 8; j++)
        #pragma unroll
        for (int i = 0; i < 4; i++) O[j][i] = 0.f;

    for (int kv0 = 0; kv0 < KVHALF; kv0 += 128) {
        const int valid = (KVHALF - kv0 < 128) ? (KVHALF - kv0) : 128;  // 128 or 32

        // S block = QW @ in_blk^T -> SXt[kv][row]
        float sacc[8][4];
        #pragma unroll
        for (int j = 0; j < 8; j++)
            #pragma unroll
            for (int i = 0; i < 4; i++) sacc[j][i] = 0.f;
        gemm_tb_in(QWt, tensor, latents, bt, kvbase + kv0, valid,
                   sacc, Bs, wm, wn, grp, qid, t);
        #pragma unroll
        for (int j = 0; j < 8; j++) {
            const int c = wn + 8*j + 2*qid;
            if (c < valid) {
                SXt[(c  )*72 + wm+grp  ] = sacc[j][0];
                SXt[(c  )*72 + wm+grp+8] = sacc[j][2];
            }
            if (c + 1 < valid) {
                SXt[(c+1)*72 + wm+grp  ] = sacc[j][1];
                SXt[(c+1)*72 + wm+grp+8] = sacc[j][3];
            }
        }
        __syncthreads();

        // online softmax: 4 threads per row
        {
            const int row = t >> 2, part = t & 3;
            const float mo = m_run[row];
            float mx = mo;
            #pragma unroll 8
            for (int i = 0; i < 32; i++) {
                const int c = part * 32 + i;
                if (c < valid) mx = fmaxf(mx, SXt[c*72 + row]);
            }
            mx = fmaxf(mx, __shfl_xor_sync(0xffffffffu, mx, 1));
            mx = fmaxf(mx, __shfl_xor_sync(0xffffffffu, mx, 2));
            float s = 0.f;
            #pragma unroll 8
            for (int i = 0; i < 32; i++) {
                const int c = part * 32 + i;
                if (c < valid) {
                    const float e = __expf(SXt[c*72 + row] - mx);
                    SXt[c*72 + row] = cf(e);
                    s += e;
                }
            }
            s += __shfl_xor_sync(0xffffffffu, s, 1);
            s += __shfl_xor_sync(0xffffffffu, s, 2);
            if (part == 0) {
                const float scale = __expf(mo - mx);
                l_run[row] = l_run[row] * scale + s;
                m_run[row] = mx;
                rsc[row]   = scale;
            }
        }
        __syncthreads();

        // rescale O, then O += P @ in_blk
        {
            const float s0 = rsc[wm+grp], s1 = rsc[wm+grp+8];
            #pragma unroll
            for (int j = 0; j < 8; j++) {
                O[j][0] *= s0; O[j][1] *= s0;
                O[j][2] *= s1; O[j][3] *= s1;
            }
        }
        gemm_nn_in(SXt, tensor, latents, bt, kvbase + kv0, valid,
                   O, Bs, wm, wn, grp, qid, t);
        __syncthreads();
    }

    // store un-normalized O + (m,l)
    if (t < 64) g_ml2[(size_t)zz * NL + t] = make_float2(m_run[t], l_run[t]);
    float* P = g_po + (size_t)zz * NL * DIMM;
    #pragma unroll
    for (int j = 0; j < 8; j++) {
        const int c = wn + 8*j + 2*qid;
        *(float2*)&P[(size_t)(wm+grp  ) * DIMM + c] = make_float2(O[j][0], O[j][1]);
        *(float2*)&P[(size_t)(wm+grp+8) * DIMM + c] = make_float2(O[j][2], O[j][3]);
    }
}

// ===========================================================================
// fp32 64x64 cores for weight precompute (256 threads)
// ===========================================================================
__device__ __forceinline__ void f32_nn_core(
    const float* __restrict__ A, const float* __restrict__ B, float* __restrict__ C,
    int lda, int ldb, int ldc, int K, float alpha, int m0, int n0)
{
    __shared__ float As[16][68];
    __shared__ float Bs[16][68];
    const int t  = threadIdx.x;
    const int tx = t & 15, ty = t >> 4;
    const int am = t >> 2, ak = (t & 3) << 2;
    const int bk = t >> 4, bn = (t & 15) << 2;
    const float* Ap = A + (size_t)(m0 + am) * lda + ak;
    const float* Bp = B + (size_t)bk * ldb + n0 + bn;
    float acc[4][4] = {};
    for (int kb = 0; kb < K; kb += 16) {
        float4 a = *(const float4*)(Ap + kb);
        float4 b = *(const float4*)(Bp + (size_t)kb * ldb);
        As[ak+0][am] = a.x; As[ak+1][am] = a.y; As[ak+2][am] = a.z; As[ak+3][am] = a.w;
        *(float4*)&Bs[bk][bn] = b;
        __syncthreads();
        #pragma unroll
        for (int k = 0; k < 16; ++k) {
            float4 av = *(const float4*)&As[k][ty << 2];
            float4 bv = *(const float4*)&Bs[k][tx << 2];
            acc[0][0] += av.x*bv.x; acc[0][1] += av.x*bv.y; acc[0][2] += av.x*bv.z; acc[0][3] += av.x*bv.w;
            acc[1][0] += av.y*bv.x; acc[1][1] += av.y*bv.y; acc[1][2] += av.y*bv.z; acc[1][3] += av.y*bv.w;
            acc[2][0] += av.z*bv.x; acc[2][1] += av.z*bv.y; acc[2][2] += av.z*bv.z; acc[2][3] += av.z*bv.w;
            acc[3][0] += av.w*bv.x; acc[3][1] += av.w*bv.y; acc[3][2] += av.w*bv.z; acc[3][3] += av.w*bv.w;
        }
        __syncthreads();
    }
    #pragma unroll
    for (int i = 0; i < 4; ++i) {
        float4 r;
        r.x = acc[i][0]*alpha; r.y = acc[i][1]*alpha; r.z = acc[i][2]*alpha; r.w = acc[i][3]*alpha;
        *(float4*)&C[(size_t)(m0 + (ty << 2) + i) * ldc + n0 + (tx << 2)] = r;
    }
}

__device__ __forceinline__ void f32_nt_core(
    const float* __restrict__ A, const float* __restrict__ Bm, float* __restrict__ C,
    int lda, int ldb, int ldc, int K, float alpha, int m0, int n0)
{
    __shared__ float As[16][68];
    __shared__ float Bs[16][68];
    const int t  = threadIdx.x;
    const int tx = t & 15, ty = t >> 4;
    const int am = t >> 2, ak = (t & 3) << 2;
    const int bn = t >> 2, bq = (t & 3) << 2;
    const float* Ap = A  + (size_t)(m0 + am) * lda + ak;
    const float* Bp = Bm + (size_t)(n0 + bn) * ldb + bq;
    float acc[4][4] = {};
    for (int kb = 0; kb < K; kb += 16) {
        float4 a = *(const float4*)(Ap + kb);
        float4 b = *(const float4*)(Bp + kb);
        As[ak+0][am] = a.x; As[ak+1][am] = a.y; As[ak+2][am] = a.z; As[ak+3][am] = a.w;
        Bs[bq+0][bn] = b.x; Bs[bq+1][bn] = b.y; Bs[bq+2][bn] = b.z; Bs[bq+3][bn] = b.w;
        __syncthreads();
        #pragma unroll
        for (int k = 0; k < 16; ++k) {
            float4 av = *(const float4*)&As[k][ty << 2];
            float4 bv = *(const float4*)&Bs[k][tx << 2];
            acc[0][0] += av.x*bv.x; acc[0][1] += av.x*bv.y; acc[0][2] += av.x*bv.z; acc[0][3] += av.x*bv.w;
            acc[1][0] += av.y*bv.x; acc[1][1] += av.y*bv.y; acc[1][2] += av.y*bv.z; acc[1][3] += av.y*bv.w;
            acc[2][0] += av.z*bv.x; acc[2][1] += av.z*bv.y; acc[2][2] += av.z*bv.z; acc[2][3] += av.z*bv.w;
            acc[3][0] += av.w*bv.x; acc[3][1] += av.w*bv.y; acc[3][2] += av.w*bv.z; acc[3][3] += av.w*bv.w;
        }
        __syncthreads();
    }
    #pragma unroll
    for (int i = 0; i < 4; ++i) {
        float4 r;
        r.x = acc[i][0]*alpha; r.y = acc[i][1]*alpha; r.z = acc[i][2]*alpha; r.w = acc[i][3]*alpha;
        *(float4*)&C[(size_t)(m0 + (ty << 2) + i) * ldc + n0 + (tx << 2)] = r;
    }
}

// k_prep: blocks 0..31 -> M_h, 32..63 -> N_h
__global__ void k_prep(const float* __restrict__ Wq, const float* __restrict__ Wkv,
                       const float* __restrict__ Wo)
{
    const int b = blockIdx.x;
    if (b < 32) {
        int h = b >> 2, sub = b & 3;
        f32_nt_core(Wq + h * 256, Wkv + h * 256, g_m + (size_t)h * DIMM * DIMM,
                    INNER, 2 * INNER, DIMM, 256, QSCALE,
                    (sub >> 1) * 64, (sub & 1) * 64);
    } else {
        int idx = b - 32;
        int h = idx >> 2, sub = idx & 3;
        f32_nn_core(Wkv + INNER + h * 256, Wo + (size_t)h * 256 * DIMM,
                    g_n + (size_t)h * DIMM * DIMM,
                    2 * INNER, DIMM, DIMM, 256, 1.0f,
                    (sub >> 1) * 64, (sub & 1) * 64);
    }
}

// ===========================================================================
// k_final_part: per (h, bt): partial_h = PI_h @ N_h, with the flash-combine
// (merge of two KV halves + 1/l) fused into the A loader. 128 threads.
// ===========================================================================
__global__ void __launch_bounds__(128) k_final_part()
{
    __shared__ float As[32][72];
    __shared__ float Bs[32][136];
    const int h = blockIdx.x, bt = blockIdx.y;
    const int z = bt * HEADS + h;
    const float* B = g_n + (size_t)h * DIMM * DIMM;
    float*       C = g_fp + (size_t)z * NL * DIMM;

    const int t    = threadIdx.x;
    const int warp = t >> 5, lane = t & 31;
    const int grp  = lane >> 2, qid = lane & 3;
    const int wm   = (warp & 1) * 32, wn = (warp >> 1) * 64;

    const int arow = t >> 1, ak0 = (t & 1) * 16;

    // combine scalars for this row (h fixed per CTA)
    float2 ml0 = g_ml2[(size_t)(z*2  ) * NL + arow];
    float2 ml1 = g_ml2[(size_t)(z*2+1) * NL + arow];
    const float mm = fmaxf(ml0.x, ml1.x);
    const float a0 = __expf(ml0.x - mm), a1 = __expf(ml1.x - mm);
    const float il = 1.0f / (ml0.y * a0 + ml1.y * a1);
    const float e0 = a0 * il, e1 = a1 * il;

    const float* O0 = g_po + (size_t)(z*2  ) * NL * DIMM + (size_t)arow * DIMM + ak0;
    const float* O1 = g_po + (size_t)(z*2+1) * NL * DIMM + (size_t)arow * DIMM + ak0;
    const int brow = t >> 2, bcol = (t & 3) * 32;
    const float* Bp = B + (size_t)brow * DIMM + bcol;

    float acc[2][8][4];
    #pragma unroll
    for (int f = 0; f < 2; f++)
        #pragma unroll
        for (int j = 0; j < 8; j++)
            #pragma unroll
            for (int i = 0; i < 4; i++) acc[f][j][i] = 0.f;

    float4 o0[4], o1[4], br[8];
    #pragma unroll
    for (int i = 0; i < 4; i++) {
        o0[i] = *(const float4*)(O0 + 4*i);
        o1[i] = *(const float4*)(O1 + 4*i);
    }
    #pragma unroll
    for (int i = 0; i < 8; i++) br[i] = *(const float4*)(Bp + 4*i);

    const int nk = DIMM / 32;   // 4
    for (int c = 0; c < nk; c++) {
        #pragma unroll
        for (int i = 0; i < 4; i++) {
            const int kc = ak0 + 4*i;
            As[kc+0][arow] = cf(e0*o0[i].x + e1*o1[i].x);
            As[kc+1][arow] = cf(e0*o0[i].y + e1*o1[i].y);
            As[kc+2][arow] = cf(e0*o0[i].z + e1*o1[i].z);
            As[kc+3][arow] = cf(e0*o0[i].w + e1*o1[i].w);
        }
        #pragma unroll
        for (int i = 0; i < 8; i++) {
            float4 v;
            v.x = cf(br[i].x); v.y = cf(br[i].y);
            v.z = cf(br[i].z); v.w = cf(br[i].w);
            *(float4*)&Bs[brow][bcol + 4*i] = v;
        }
        __syncthreads();
        if (c + 1 < nk) {
            #pragma unroll
            for (int i = 0; i < 4; i++) {
                o0[i] = *(const float4*)(O0 + (c+1)*32 + 4*i);
                o1[i] = *(const float4*)(O1 + (c+1)*32 + 4*i);
            }
            const float* Bp2 = Bp + (size_t)(c + 1) * 32 * DIMM;
            #pragma unroll
            for (int i = 0; i < 8; i++) br[i] = *(const float4*)(Bp2 + 4*i);
        }
        #pragma unroll
        for (int kk = 0; kk < 32; kk += 8) {
            unsigned a[2][4], b[8][2];
            #pragma unroll
            for (int f = 0; f < 2; f++) {
                a[f][0] = __float_as_uint(As[kk+qid  ][wm+16*f+grp  ]);
                a[f][1] = __float_as_uint(As[kk+qid  ][wm+16*f+grp+8]);
                a[f][2] = __float_as_uint(As[kk+qid+4][wm+16*f+grp  ]);
                a[f][3] = __float_as_uint(As[kk+qid+4][wm+16*f+grp+8]);
            }
            #pragma unroll
            for (int j = 0; j < 8; j++) {
                b[j][0] = __float_as_uint(Bs[kk+qid  ][wn+8*j+grp]);
                b[j][1] = __float_as_uint(Bs[kk+qid+4][wn+8*j+grp]);
            }
            #pragma unroll
            for (int f = 0; f < 2; f++)
                #pragma unroll
                for (int j = 0; j < 8; j++) mma8(acc[f][j], a[f], b[j]);
        }
        __syncthreads();
    }
    #pragma unroll
    for (int f = 0; f < 2; f++) {
        const int r0 = wm + 16*f + grp;
        #pragma unroll
        for (int j = 0; j < 8; j++) {
            const int col = wn + 8*j + 2*qid;
            *(float2*)&C[(size_t)r0 * DIMM + col] = make_float2(acc[f][j][0], acc[f][j][1]);
            *(float2*)&C[(size_t)(r0+8) * DIMM + col] = make_float2(acc[f][j][2], acc[f][j][3]);
        }
    }
}

// reduce 8 per-head partials -> out
__global__ void k_final_red(float* __restrict__ out)
{
    const int i = blockIdx.x * 256 + threadIdx.x;   // float4 index, 32768 total
    const int bt = i >> 11, inner = i & 2047;
    const float4* fp = (const float4*)g_fp;
    float4 r = make_float4(0.f, 0.f, 0.f, 0.f);
    #pragma unroll
    for (int h = 0; h < 8; h++) {
        float4 a = fp[((size_t)bt * 8 + h) * 2048 + inner];
        r.x += a.x; r.y += a.y; r.z += a.z; r.w += a.w;
    }
    ((float4*)out)[i] = r;
}

// ---------------------------------------------------------------------------

#define FLASH_SMEM ((2*128*72 + 32*136 + 3*64) * 4)

extern "C" void kernel_launch(void* const* d_in, const int* in_sizes, int n_in,
                              void* d_out, int out_size)
{
    const float* tensor  = (const float*)d_in[0];
    const float* latents = (const float*)d_in[1];
    const float* Wq      = (const float*)d_in[2];
    const float* Wkv     = (const float*)d_in[3];
    const float* Wo      = (const float*)d_in[4];
    float*       out     = (float*)d_out;

    (void)in_sizes; (void)n_in; (void)out_size;

    cudaFuncSetAttribute(k_flash, cudaFuncAttributeMaxDynamicSharedMemorySize, FLASH_SMEM);

    k_prep      <<<64, 256>>>(Wq, Wkv, Wo);
    k_flash     <<<2 * BTT * HEADS, 256, FLASH_SMEM>>>(tensor, latents);
    k_final_part<<<dim3(HEADS, BTT), 128>>>();
    k_final_red <<<(BTT * NL * DIMM / 4) / 256, 256>>>(out);
}